// round 2
// baseline (speedup 1.0000x reference)
#include <cuda_runtime.h>

// ---------------- problem constants ----------------
// x:(32,3,128,128)  enc1->(32,128,64,64)  enc2->(32,128,32,32) pool->(32,128,8,8)
// proj-> z_e (32,64,8,8)  VQ K=512,D=64  dproj->(32,128,8,8) up x16 -> dconv1 -> dconv2 -> (32,3,128,128)

typedef unsigned long long u64;
__device__ __forceinline__ u64 pk2(float lo, float hi) {
    u64 r; asm("mov.b64 %0,{%1,%2};" : "=l"(r) : "f"(lo), "f"(hi)); return r;
}
__device__ __forceinline__ u64 ffma2(u64 a, u64 b, u64 c) {
    u64 d; asm("fma.rn.f32x2 %0,%1,%2,%3;" : "=l"(d) : "l"(a), "l"(b), "l"(c)); return d;
}
__device__ __forceinline__ float2 upk2(u64 v) {
    float2 f; asm("mov.b64 {%0,%1},%2;" : "=f"(f.x), "=f"(f.y) : "l"(v)); return f;
}

// ---------------- device scratch (no allocations allowed) ----------------
__device__ float g_h1[32 * 128 * 64 * 64];    // encoder conv1 output (64 MB)
__device__ float g_hp[32 * 128 * 8 * 8];      // pooled encoder features
__device__ float g_y [32 * 128 * 8 * 8];      // dproj output (relu'd)
__device__ float g_r9[32 * 9 * 128 * 64];     // dconv1: 9 distinct values per 16x16 block
__device__ float g_w25[25 * 128 * 128];       // pre-summed dconv1 weight subsets [m][ic][oc]
__device__ int   g_idx[2048];
__device__ float g_loss;

// ================= encoder conv1: 3->128, 3x3, s2, p1, relu (oc-pair packed FFMA2) =================
__global__ void enc1_kernel(const float* __restrict__ x,
                            const float* __restrict__ w,
                            const float* __restrict__ bias) {
    __shared__ float ws[3456]; // [c][ky][kx][128]
    int oy = blockIdx.x, b = blockIdx.y;
    int tid = threadIdx.x;
    for (int e = tid; e < 3456; e += 256) {
        int oc = e & 127; int t = e >> 7;
        int c = t / 9; int r = t - c * 9; int ky = r / 3, kx = r - ky * 3;
        ws[e] = w[((oc * 3 + c) * 3 + ky) * 3 + kx];
    }
    __syncthreads();
    int ox = tid & 63, ocg = tid >> 6;
    u64 acc2[16]; // oc pairs (ocg*32 + 2i, 2i+1)
#pragma unroll
    for (int i = 0; i < 16; i++)
        acc2[i] = pk2(__ldg(bias + ocg * 32 + 2 * i), __ldg(bias + ocg * 32 + 2 * i + 1));
    const float* xb = x + b * 3 * 128 * 128;
#pragma unroll
    for (int c = 0; c < 3; c++) {
#pragma unroll
        for (int ky = 0; ky < 3; ky++) {
            int iy = 2 * oy + ky - 1;
#pragma unroll
            for (int kx = 0; kx < 3; kx++) {
                int ix = 2 * ox + kx - 1;
                float xv = 0.f;
                if ((unsigned)iy < 128u && (unsigned)ix < 128u)
                    xv = __ldg(xb + (c * 128 + iy) * 128 + ix);
                u64 xd = pk2(xv, xv);
                const ulonglong2* wp =
                    (const ulonglong2*)&ws[((c * 3 + ky) * 3 + kx) * 128 + ocg * 32];
#pragma unroll
                for (int q = 0; q < 8; q++) {
                    ulonglong2 wv = wp[q];
                    acc2[2 * q]     = ffma2(wv.x, xd, acc2[2 * q]);
                    acc2[2 * q + 1] = ffma2(wv.y, xd, acc2[2 * q + 1]);
                }
            }
        }
    }
    float* op = g_h1 + ((b * 128 + ocg * 32) * 64 + oy) * 64 + ox;
#pragma unroll
    for (int i = 0; i < 16; i++) {
        float2 v = upk2(acc2[i]);
        op[(2 * i) * 4096]     = fmaxf(v.x, 0.f);
        op[(2 * i + 1) * 4096] = fmaxf(v.y, 0.f);
    }
}

// ================= encoder conv2 (128->128, 3x3, s2, p1) + relu + 4x4 avg pool =================
// row-pair packed FFMA2; weights stored duplicated in smem so packed operands are free.
// grid (32 b, 4 ocg, 8 gy), 256 thr.
__global__ void enc2_pool_kernel(const float* __restrict__ w,
                                 const float* __restrict__ bias) {
    __shared__ float sm[9360];
    float* s_in = sm;          // 8 ic x 9 rows x 66 cols = 4752
    float* s_w2 = sm + 4752;   // 8 ic x 9 taps x 32 oc x2(dup) = 4608
    int b = blockIdx.x, ocg = blockIdx.y, gy = blockIdx.z;
    int tid = threadIdx.x;
    int ox = tid & 31, ocq = tid >> 5; // thread owns 4 oc (= 4 dup pairs), 4 rows (2 packed pairs)
    u64 accA[4], accB[4]; // accA: rows(0,1), accB: rows(2,3), for oc i
#pragma unroll
    for (int i = 0; i < 4; i++) {
        float bv = __ldg(bias + ocg * 32 + ocq * 4 + i);
        accA[i] = pk2(bv, bv); accB[i] = pk2(bv, bv);
    }

    for (int ch = 0; ch < 16; ch++) {
        __syncthreads();
        for (int e = tid; e < 4752; e += 256) {
            int ic = e / 594; int rem = e - ic * 594;
            int rr = rem / 66; int cc = rem - rr * 66;
            int iy = gy * 8 - 1 + rr; int ix = cc - 1;
            float v = 0.f;
            if ((unsigned)iy < 64u && (unsigned)ix < 64u)
                v = g_h1[((b * 128 + ch * 8 + ic) * 64 + iy) * 64 + ix];
            s_in[e] = v;
        }
        for (int e = tid; e < 4608; e += 256) {
            int ic = e / 576; int rem = e - ic * 576;
            int tap = rem >> 6; int oc2 = rem & 63; int ocl = oc2 >> 1;
            int ky = tap / 3, kx = tap - ky * 3;
            s_w2[e] = __ldg(w + (((ocg * 32 + ocl) * 128 + ch * 8 + ic) * 3 + ky) * 3 + kx);
        }
        __syncthreads();
#pragma unroll 2
        for (int ic = 0; ic < 8; ic++) {
            const float* sib = s_in + ic * 594 + 2 * ox;
            const float* swb = s_w2 + ic * 576 + ocq * 8;
#pragma unroll
            for (int ky = 0; ky < 3; ky++) {
#pragma unroll
                for (int kx = 0; kx < 3; kx++) {
                    const ulonglong2* wp = (const ulonglong2*)(swb + (ky * 3 + kx) * 64);
                    ulonglong2 wa = wp[0]; // oc0 dup, oc1 dup
                    ulonglong2 wb = wp[1]; // oc2 dup, oc3 dup
                    float iv0 = sib[(0 + ky) * 66 + kx];
                    float iv1 = sib[(2 + ky) * 66 + kx];
                    float iv2 = sib[(4 + ky) * 66 + kx];
                    float iv3 = sib[(6 + ky) * 66 + kx];
                    u64 p01 = pk2(iv0, iv1);
                    u64 p23 = pk2(iv2, iv3);
                    accA[0] = ffma2(wa.x, p01, accA[0]); accB[0] = ffma2(wa.x, p23, accB[0]);
                    accA[1] = ffma2(wa.y, p01, accA[1]); accB[1] = ffma2(wa.y, p23, accB[1]);
                    accA[2] = ffma2(wb.x, p01, accA[2]); accB[2] = ffma2(wb.x, p23, accB[2]);
                    accA[3] = ffma2(wb.y, p01, accA[3]); accB[3] = ffma2(wb.y, p23, accB[3]);
                }
            }
        }
    }
    // relu + pool (4 rows reduced in regs, 4 cols via shared)
    __syncthreads();
    float* s_red = sm; // 32 oc x 33
#pragma unroll
    for (int i = 0; i < 4; i++) {
        float2 a01 = upk2(accA[i]);
        float2 a23 = upk2(accB[i]);
        float s = fmaxf(a01.x, 0.f) + fmaxf(a01.y, 0.f) + fmaxf(a23.x, 0.f) + fmaxf(a23.y, 0.f);
        s_red[(ocq * 4 + i) * 33 + ox] = s;
    }
    __syncthreads();
    {
        int oc = tid & 31, gxp = tid >> 5;
        float s = 0.f;
#pragma unroll
        for (int j = 0; j < 4; j++) s += s_red[oc * 33 + gxp * 4 + j];
        g_hp[((b * 128 + ocg * 32 + oc) * 8 + gy) * 8 + gxp] = s * (1.f / 16.f);
    }
}

// ================= proj 1x1: 128 -> 64 =================
__global__ void proj_kernel(const float* __restrict__ w,
                            const float* __restrict__ bias,
                            float* __restrict__ zout) {
    __shared__ float s_hp[8192]; // [hc][pos]
    int b = blockIdx.x, tid = threadIdx.x;
    for (int e = tid; e < 8192; e += 256) s_hp[e] = g_hp[b * 8192 + e];
    __syncthreads();
    int pos = tid & 63, dg = tid >> 6;
    for (int dl = 0; dl < 16; dl++) {
        int d = dg * 16 + dl;
        float acc = __ldg(bias + d);
        const float* wr = w + d * 128;
#pragma unroll 8
        for (int hc = 0; hc < 128; hc++) acc += __ldg(wr + hc) * s_hp[hc * 64 + pos];
        zout[(b * 64 + d) * 64 + pos] = acc;
    }
}

// ================= vector quantizer =================
__global__ void zero_loss_kernel() { g_loss = 0.f; }

__global__ void vq_kernel(const float* __restrict__ z,
                          const float* __restrict__ cb,
                          float* __restrict__ idx_out) {
    __shared__ float s_z[64];
    __shared__ float sv[128];
    __shared__ int   si[128];
    int n = blockIdx.x; int b = n >> 6, pos = n & 63;
    int tid = threadIdx.x;
    if (tid < 64) s_z[tid] = z[(b * 64 + tid) * 64 + pos];
    __syncthreads();
    float bestv = 3.4e38f; int besti = 0;
    for (int kk = 0; kk < 4; kk++) {
        int k = tid * 4 + kk;
        const float* cr = cb + k * 64;
        float s = 0.f;
#pragma unroll 8
        for (int d = 0; d < 64; d++) { float df = s_z[d] - __ldg(cr + d); s += df * df; }
        if (s < bestv) { bestv = s; besti = k; }
    }
    sv[tid] = bestv; si[tid] = besti;
    __syncthreads();
    for (int st = 64; st > 0; st >>= 1) {
        if (tid < st) {
            float v2 = sv[tid + st]; int i2 = si[tid + st];
            if (v2 < sv[tid] || (v2 == sv[tid] && i2 < si[tid])) { sv[tid] = v2; si[tid] = i2; }
        }
        __syncthreads();
    }
    if (tid == 0) {
        g_idx[n] = si[0];
        idx_out[n] = (float)si[0];
        atomicAdd(&g_loss, sv[0]);
    }
}

__global__ void finalize_loss_kernel(float* __restrict__ out) {
    out[0] = g_loss * (1.25f / 131072.f);
}

// ================= dproj 1x1: 64 -> 128, relu (pre-upsample) =================
__global__ void dproj_kernel(const float* __restrict__ cb,
                             const float* __restrict__ w,
                             const float* __restrict__ bias) {
    __shared__ float s_zq[4096]; // [d][pos]
    __shared__ int   s_i[64];
    int b = blockIdx.x, tid = threadIdx.x;
    if (tid < 64) s_i[tid] = g_idx[b * 64 + tid];
    __syncthreads();
    for (int e = tid; e < 4096; e += 256) {
        int d = e >> 6, pos = e & 63;
        s_zq[e] = __ldg(cb + s_i[pos] * 64 + d);
    }
    __syncthreads();
    int pos = tid & 63, hg = tid >> 6;
    for (int h = 0; h < 32; h++) {
        int hc = hg * 32 + h;
        float acc = __ldg(bias + hc);
        const float* wr = w + hc * 64;
#pragma unroll 8
        for (int d = 0; d < 64; d++) acc += __ldg(wr + d) * s_zq[d * 64 + pos];
        g_y[b * 8192 + hc * 64 + pos] = fmaxf(acc, 0.f);
    }
}

// ================= dconv1 weight-subset precompute =================
__global__ void w25_kernel(const float* __restrict__ w) {
    int g = blockIdx.x * 256 + threadIdx.x;
    if (g >= 25 * 16384) return;
    int m = g >> 14; int r = g & 16383; int ic = r & 127; int oc = r >> 7;
    int sy = m / 5, sx = m - sy * 5;
    const int mask[5] = {1, 4, 3, 6, 7};
    float s = 0.f;
    for (int j = 0; j < 3; j++) if ((mask[sy] >> j) & 1)
        for (int i = 0; i < 3; i++) if ((mask[sx] >> i) & 1)
            s += __ldg(w + ((oc * 128 + ic) * 3 + j) * 3 + i);
    g_w25[(m * 128 + ic) * 128 + oc] = s;
}

// ================= dconv1 on block-constant input (oc-pair packed FFMA2) =================
// grid (32 b, 9 vt), 256 thr.
__global__ void dconv1_blocks_kernel(const float* __restrict__ bias) {
    __shared__ float s_y[8192]; // [ic][pos]
    int b = blockIdx.x, vt = blockIdx.y;
    int tid = threadIdx.x;
    for (int e = tid; e < 8192; e += 256) s_y[e] = g_y[b * 8192 + e];
    __syncthreads();

    int lane = tid & 31;
    int ocb = (tid >> 5) * 16;
    int ty = vt / 3, tx = vt - ty * 3;

    int nyp, ys[2], ydy[2];
    if (ty == 0)      { nyp = 2; ys[0] = 0; ydy[0] = -1; ys[1] = 3; ydy[1] = 0; }
    else if (ty == 1) { nyp = 1; ys[0] = 4; ydy[0] = 0;  ys[1] = 0; ydy[1] = 0; }
    else              { nyp = 2; ys[0] = 2; ydy[0] = 0;  ys[1] = 1; ydy[1] = 1; }
    int nxp, xs[2], xdx[2];
    if (tx == 0)      { nxp = 2; xs[0] = 0; xdx[0] = -1; xs[1] = 3; xdx[1] = 0; }
    else if (tx == 1) { nxp = 1; xs[0] = 4; xdx[0] = 0;  xs[1] = 0; xdx[1] = 0; }
    else              { nxp = 2; xs[0] = 2; xdx[0] = 0;  xs[1] = 1; xdx[1] = 1; }

    u64 acc0[8], acc1[8]; // oc pairs (ocb+2i, ocb+2i+1) for pos0 / pos1
#pragma unroll
    for (int i = 0; i < 8; i++) {
        u64 bv = pk2(__ldg(bias + ocb + 2 * i), __ldg(bias + ocb + 2 * i + 1));
        acc0[i] = bv; acc1[i] = bv;
    }

    int pos0 = lane, pos1 = lane + 32;
    int gy0 = pos0 >> 3, gx0 = pos0 & 7;
    int gy1 = pos1 >> 3, gx1 = pos1 & 7;

    for (int a = 0; a < nyp; a++) {
        for (int c = 0; c < nxp; c++) {
            int m = ys[a] * 5 + xs[c];
            int dy = ydy[a], dx = xdx[c];
            int ny0 = gy0 + dy, nx0 = gx0 + dx;
            int ny1 = gy1 + dy, nx1 = gx1 + dx;
            bool v0 = ((unsigned)ny0 < 8u) && ((unsigned)nx0 < 8u);
            bool v1 = ((unsigned)ny1 < 8u) && ((unsigned)nx1 < 8u);
            int np0 = ny0 * 8 + nx0, np1 = ny1 * 8 + nx1;
            const float* wbase = g_w25 + (m * 128) * 128 + ocb;
#pragma unroll 4
            for (int ic = 0; ic < 128; ic++) {
                float yv0 = v0 ? s_y[ic * 64 + np0] : 0.f;
                float yv1 = v1 ? s_y[ic * 64 + np1] : 0.f;
                u64 d0 = pk2(yv0, yv0);
                u64 d1 = pk2(yv1, yv1);
                const ulonglong2* wp = (const ulonglong2*)(wbase + ic * 128);
#pragma unroll
                for (int q = 0; q < 4; q++) {
                    ulonglong2 wv = __ldg(wp + q); // oc (4q,4q+1),(4q+2,4q+3)
                    acc0[2 * q]     = ffma2(wv.x, d0, acc0[2 * q]);
                    acc1[2 * q]     = ffma2(wv.x, d1, acc1[2 * q]);
                    acc0[2 * q + 1] = ffma2(wv.y, d0, acc0[2 * q + 1]);
                    acc1[2 * q + 1] = ffma2(wv.y, d1, acc1[2 * q + 1]);
                }
            }
        }
    }
    float* op = g_r9 + ((size_t)(b * 9 + vt) * 128 + ocb) * 64;
#pragma unroll
    for (int i = 0; i < 8; i++) {
        float2 a0 = upk2(acc0[i]);
        float2 a1 = upk2(acc1[i]);
        op[(2 * i) * 64 + pos0]     = fmaxf(a0.x, 0.f);
        op[(2 * i + 1) * 64 + pos0] = fmaxf(a0.y, 0.f);
        op[(2 * i) * 64 + pos1]     = fmaxf(a1.x, 0.f);
        op[(2 * i + 1) * 64 + pos1] = fmaxf(a1.y, 0.f);
    }
}

// ================= dconv2 1x1 (128->3) on 9 block values + scatter =================
__global__ void dconv2_scatter_kernel(const float* __restrict__ w,
                                      const float* __restrict__ bias,
                                      float* __restrict__ xhat) {
    __shared__ float s_r[1152]; // [vt][oc]
    __shared__ float s_v[27];   // [vt][co]
    int pos = blockIdx.x, b = blockIdx.y;
    int tid = threadIdx.x;
    for (int e = tid; e < 1152; e += 128) {
        int vt = e >> 7, oc = e & 127;
        s_r[e] = g_r9[((size_t)(b * 9 + vt) * 128 + oc) * 64 + pos];
    }
    __syncthreads();
    if (tid < 27) {
        int vt = tid / 3, co = tid - vt * 3;
        float acc = __ldg(bias + co);
        const float* wr = w + co * 128;
        const float* rr = s_r + vt * 128;
#pragma unroll 8
        for (int oc = 0; oc < 128; oc++) acc += __ldg(wr + oc) * rr[oc];
        s_v[tid] = acc;
    }
    __syncthreads();
    int gy = pos >> 3, gx = pos & 7;
    for (int pp = tid; pp < 256; pp += 128) {
        int ly = pp >> 4, lx = pp & 15;
        int ty2 = (ly == 0) ? 0 : ((ly == 15) ? 2 : 1);
        int tx2 = (lx == 0) ? 0 : ((lx == 15) ? 2 : 1);
        int vtp = ty2 * 3 + tx2;
        int py = gy * 16 + ly, px = gx * 16 + lx;
#pragma unroll
        for (int co = 0; co < 3; co++)
            xhat[((b * 3 + co) * 128 + py) * 128 + px] = s_v[vtp * 3 + co];
    }
}

// ================= launch =================
extern "C" void kernel_launch(void* const* d_in, const int* in_sizes, int n_in,
                              void* d_out, int out_size) {
    const float* x   = (const float*)d_in[0];
    const float* ew1 = (const float*)d_in[1];
    const float* eb1 = (const float*)d_in[2];
    const float* ew2 = (const float*)d_in[3];
    const float* eb2 = (const float*)d_in[4];
    const float* pw  = (const float*)d_in[5];
    const float* pb  = (const float*)d_in[6];
    const float* cb  = (const float*)d_in[7];
    const float* dpw = (const float*)d_in[8];
    const float* dpb = (const float*)d_in[9];
    const float* dw1 = (const float*)d_in[10];
    const float* db1 = (const float*)d_in[11];
    const float* dw2 = (const float*)d_in[12];
    const float* db2 = (const float*)d_in[13];

    float* out   = (float*)d_out;
    float* xhat  = out;               // 32*3*128*128 = 1572864
    float* idxo  = out + 1572864;     // 32*8*8       = 2048
    float* losso = out + 1574912;     // 1
    float* zeo   = out + 1574913;     // 32*64*8*8    = 131072

    enc1_kernel<<<dim3(64, 32), 256>>>(x, ew1, eb1);
    enc2_pool_kernel<<<dim3(32, 4, 8), 256>>>(ew2, eb2);
    proj_kernel<<<32, 256>>>(pw, pb, zeo);
    zero_loss_kernel<<<1, 1>>>();
    vq_kernel<<<2048, 128>>>(zeo, cb, idxo);
    finalize_loss_kernel<<<1, 1>>>(losso);
    w25_kernel<<<1600, 256>>>(dw1);
    dproj_kernel<<<32, 256>>>(cb, dpw, dpb);
    dconv1_blocks_kernel<<<dim3(32, 9), 256>>>(db1);
    dconv2_scatter_kernel<<<dim3(64, 32), 128>>>(dw2, db2, xhat);
}

// round 4
// speedup vs baseline: 1.5329x; 1.5329x over previous
#include <cuda_runtime.h>

// ---------------- problem constants ----------------
// x:(32,3,128,128)  enc1->(32,128,64,64)  enc2->(32,128,32,32) pool->(32,128,8,8)
// proj-> z_e (32,64,8,8)  VQ K=512,D=64  dproj->(32,128,8,8) up x16 -> dconv1 -> dconv2 -> (32,3,128,128)

// ---------------- device scratch (no allocations allowed) ----------------
__device__ float g_h1[32 * 128 * 64 * 64];    // encoder conv1 output (64 MB)
__device__ float g_hp[32 * 128 * 8 * 8];      // pooled encoder features
__device__ float g_y [32 * 128 * 8 * 8];      // dproj output (relu'd)
__device__ float g_r9[32 * 9 * 128 * 64];     // dconv1: 9 distinct values per 16x16 block
__device__ float g_w25[25 * 128 * 128];       // pre-summed dconv1 weight subsets [m][ic][oc]
__device__ int   g_idx[2048];
__device__ float g_loss;

// ================= encoder conv1: 3->128, 3x3, stride 2, pad 1, relu =================
// grid (64 oy, 32 b), 256 thr: ox = tid&63, ocg = tid>>6 (4 groups of 32 oc)
__global__ void enc1_kernel(const float* __restrict__ x,
                            const float* __restrict__ w,
                            const float* __restrict__ bias) {
    __shared__ float ws[3456]; // [c][ky][kx][128]
    int oy = blockIdx.x, b = blockIdx.y;
    int tid = threadIdx.x;
    for (int e = tid; e < 3456; e += 256) {
        int oc = e & 127; int t = e >> 7;
        int c = t / 9; int r = t - c * 9; int ky = r / 3, kx = r - ky * 3;
        ws[e] = w[((oc * 3 + c) * 3 + ky) * 3 + kx];
    }
    __syncthreads();
    int ox = tid & 63, ocg = tid >> 6;
    float acc[32];
#pragma unroll
    for (int i = 0; i < 32; i++) acc[i] = __ldg(bias + ocg * 32 + i);
    const float* xb = x + b * 3 * 128 * 128;
#pragma unroll
    for (int c = 0; c < 3; c++) {
#pragma unroll
        for (int ky = 0; ky < 3; ky++) {
            int iy = 2 * oy + ky - 1;
#pragma unroll
            for (int kx = 0; kx < 3; kx++) {
                int ix = 2 * ox + kx - 1;
                float xv = 0.f;
                if ((unsigned)iy < 128u && (unsigned)ix < 128u)
                    xv = __ldg(xb + (c * 128 + iy) * 128 + ix);
                const float* wp = &ws[((c * 3 + ky) * 3 + kx) * 128 + ocg * 32];
#pragma unroll
                for (int q = 0; q < 8; q++) {
                    float4 wv = *(const float4*)(wp + q * 4);
                    acc[q * 4 + 0] += wv.x * xv;
                    acc[q * 4 + 1] += wv.y * xv;
                    acc[q * 4 + 2] += wv.z * xv;
                    acc[q * 4 + 3] += wv.w * xv;
                }
            }
        }
    }
    float* op = g_h1 + ((b * 128 + ocg * 32) * 64 + oy) * 64 + ox;
#pragma unroll
    for (int i = 0; i < 32; i++) op[i * 64 * 64] = fmaxf(acc[i], 0.f);
}

// ================= encoder conv2 (128->128, 3x3, s2, p1) + relu + 4x4 avg pool (fused) =================
// Deep register blocking: 128 thr; thread owns 8 oc x 2 rows x 2 cols = 32 acc.
// Per tap: 32B weights + 16B inputs per 32 FMA = 1.5 B/FMA (< 2.0 crossbar budget) -> FMA-bound.
// grid (32 b, 4 ocg, 8 gy): block covers 32 oc x 4 out rows x 32 out cols, pools to one gy row.
__global__ void __launch_bounds__(128) enc2_pool_kernel(const float* __restrict__ w,
                                                        const float* __restrict__ bias) {
    __shared__ float sm[7056];
    float* s_in = sm;          // 8 ic x 9 rows x 66 cols = 4752
    float* s_w  = sm + 4752;   // 8 ic x 9 taps x 32 oc  = 2304
    int b = blockIdx.x, ocg = blockIdx.y, gy = blockIdx.z;
    int tid = threadIdx.x;
    int colg = tid & 15;          // 2 cols each: ox = 2*colg + {0,1}
    int rowg = (tid >> 4) & 1;    // 2 rows each: row = rowg*2 + {0,1}
    int ocq  = tid >> 5;          // 8 oc each:   oc  = ocq*8 + i

    float acc[8][2][2]; // [oc][row][col]
#pragma unroll
    for (int i = 0; i < 8; i++) {
        float bv = __ldg(bias + ocg * 32 + ocq * 8 + i);
#pragma unroll
        for (int r = 0; r < 2; r++) { acc[i][r][0] = bv; acc[i][r][1] = bv; }
    }

    for (int ch = 0; ch < 16; ch++) {
        __syncthreads();
        for (int e = tid; e < 4752; e += 128) {
            int ic = e / 594; int rem = e - ic * 594;
            int rr = rem / 66; int cc = rem - rr * 66;
            int iy = gy * 8 - 1 + rr; int ix = cc - 1;
            float v = 0.f;
            if ((unsigned)iy < 64u && (unsigned)ix < 64u)
                v = g_h1[((b * 128 + ch * 8 + ic) * 64 + iy) * 64 + ix];
            s_in[e] = v;
        }
        for (int e = tid; e < 2304; e += 128) {
            int ic = e / 288; int rem = e - ic * 288;
            int tap = rem >> 5; int ocl = rem & 31;
            int ky = tap / 3, kx = tap - ky * 3;
            s_w[e] = __ldg(w + (((ocg * 32 + ocl) * 128 + ch * 8 + ic) * 3 + ky) * 3 + kx);
        }
        __syncthreads();
#pragma unroll 2
        for (int ic = 0; ic < 8; ic++) {
            const float* sib = s_in + ic * 594 + 4 * colg;
            const float* swb = s_w + ic * 288 + ocq * 8;
#pragma unroll
            for (int ky = 0; ky < 3; ky++) {
                const float* r0 = sib + (2 * (rowg * 2 + 0) + ky) * 66;
                const float* r1 = sib + (2 * (rowg * 2 + 1) + ky) * 66;
#pragma unroll
                for (int kx = 0; kx < 3; kx++) {
                    float4 w0 = *(const float4*)(swb + (ky * 3 + kx) * 32);
                    float4 w1 = *(const float4*)(swb + (ky * 3 + kx) * 32 + 4);
                    float in00 = r0[kx], in01 = r0[kx + 2];
                    float in10 = r1[kx], in11 = r1[kx + 2];
                    float wreg[8] = {w0.x, w0.y, w0.z, w0.w, w1.x, w1.y, w1.z, w1.w};
#pragma unroll
                    for (int i = 0; i < 8; i++) {
                        acc[i][0][0] += wreg[i] * in00;
                        acc[i][0][1] += wreg[i] * in01;
                        acc[i][1][0] += wreg[i] * in10;
                        acc[i][1][1] += wreg[i] * in11;
                    }
                }
            }
        }
    }
    // relu + pool: thread reduces its 2 rows, cross-thread via shared
    __syncthreads();
    float* s_red = sm; // [rowg][oc][col] with rowg stride 1073 (conflict-free), oc stride 33
#pragma unroll
    for (int i = 0; i < 8; i++) {
#pragma unroll
        for (int c = 0; c < 2; c++) {
            float s = fmaxf(acc[i][0][c], 0.f) + fmaxf(acc[i][1][c], 0.f);
            s_red[rowg * 1073 + (ocq * 8 + i) * 33 + 2 * colg + c] = s;
        }
    }
    __syncthreads();
    for (int t = tid; t < 256; t += 128) {
        int oc = t >> 3, gx = t & 7;
        float s = 0.f;
#pragma unroll
        for (int rg = 0; rg < 2; rg++)
#pragma unroll
            for (int j = 0; j < 4; j++) s += s_red[rg * 1073 + oc * 33 + gx * 4 + j];
        g_hp[((b * 128 + ocg * 32 + oc) * 8 + gy) * 8 + gx] = s * (1.f / 16.f);
    }
}

// ================= proj 1x1: 128 -> 64, writes z_e straight into d_out slot =================
__global__ void proj_kernel(const float* __restrict__ w,
                            const float* __restrict__ bias,
                            float* __restrict__ zout) {
    __shared__ float s_hp[8192]; // [hc][pos]
    int b = blockIdx.x, tid = threadIdx.x;
    for (int e = tid; e < 8192; e += 256) s_hp[e] = g_hp[b * 8192 + e];
    __syncthreads();
    int pos = tid & 63, dg = tid >> 6;
    for (int dl = 0; dl < 16; dl++) {
        int d = dg * 16 + dl;
        float acc = __ldg(bias + d);
        const float* wr = w + d * 128;
#pragma unroll 8
        for (int hc = 0; hc < 128; hc++) acc += __ldg(wr + hc) * s_hp[hc * 64 + pos];
        zout[(b * 64 + d) * 64 + pos] = acc;
    }
}

// ================= vector quantizer: argmin over 512 codes + loss partial =================
__global__ void zero_loss_kernel() { g_loss = 0.f; }

__global__ void vq_kernel(const float* __restrict__ z,  // z_e in d_out, layout [b][d][pos]
                          const float* __restrict__ cb,
                          float* __restrict__ idx_out) {
    __shared__ float s_z[64];
    __shared__ float sv[128];
    __shared__ int   si[128];
    int n = blockIdx.x; int b = n >> 6, pos = n & 63;
    int tid = threadIdx.x;
    if (tid < 64) s_z[tid] = z[(b * 64 + tid) * 64 + pos];
    __syncthreads();
    float bestv = 3.4e38f; int besti = 0;
    for (int kk = 0; kk < 4; kk++) {
        int k = tid * 4 + kk;
        const float* cr = cb + k * 64;
        float s = 0.f;
#pragma unroll 8
        for (int d = 0; d < 64; d++) { float df = s_z[d] - __ldg(cr + d); s += df * df; }
        if (s < bestv) { bestv = s; besti = k; }
    }
    sv[tid] = bestv; si[tid] = besti;
    __syncthreads();
    for (int st = 64; st > 0; st >>= 1) {
        if (tid < st) {
            float v2 = sv[tid + st]; int i2 = si[tid + st];
            if (v2 < sv[tid] || (v2 == sv[tid] && i2 < si[tid])) { sv[tid] = v2; si[tid] = i2; }
        }
        __syncthreads();
    }
    if (tid == 0) {
        g_idx[n] = si[0];
        idx_out[n] = (float)si[0];
        atomicAdd(&g_loss, sv[0]);
    }
}

__global__ void finalize_loss_kernel(float* __restrict__ out) {
    // vq_loss = (1 + 0.25) * mean((z_q - z_e)^2) ; mean over 2048*64 elements
    out[0] = g_loss * (1.25f / 131072.f);
}

// ================= dproj 1x1: 64 -> 128 on quantized codes, relu (pre-upsample) =================
__global__ void dproj_kernel(const float* __restrict__ cb,
                             const float* __restrict__ w,
                             const float* __restrict__ bias) {
    __shared__ float s_zq[4096]; // [d][pos]
    __shared__ int   s_i[64];
    int b = blockIdx.x, tid = threadIdx.x;
    if (tid < 64) s_i[tid] = g_idx[b * 64 + tid];
    __syncthreads();
    for (int e = tid; e < 4096; e += 256) {
        int d = e >> 6, pos = e & 63;
        s_zq[e] = __ldg(cb + s_i[pos] * 64 + d);
    }
    __syncthreads();
    int pos = tid & 63, hg = tid >> 6;
    for (int h = 0; h < 32; h++) {
        int hc = hg * 32 + h;
        float acc = __ldg(bias + hc);
        const float* wr = w + hc * 64;
#pragma unroll 8
        for (int d = 0; d < 64; d++) acc += __ldg(wr + d) * s_zq[d * 64 + pos];
        g_y[b * 8192 + hc * 64 + pos] = fmaxf(acc, 0.f); // relu(upsample(y)) == upsample(relu(y))
    }
}

// ================= dconv1 weight-subset precompute: 25 matrices [m][ic][oc] =================
// subset index: 0:{0} 1:{2} 2:{0,1} 3:{1,2} 4:{0,1,2};  m = sy*5 + sx
__global__ void w25_kernel(const float* __restrict__ w) {
    int g = blockIdx.x * 256 + threadIdx.x;
    if (g >= 25 * 16384) return;
    int m = g >> 14; int r = g & 16383; int ic = r & 127; int oc = r >> 7;
    int sy = m / 5, sx = m - sy * 5;
    const int mask[5] = {1, 4, 3, 6, 7};
    float s = 0.f;
    for (int j = 0; j < 3; j++) if ((mask[sy] >> j) & 1)
        for (int i = 0; i < 3; i++) if ((mask[sx] >> i) & 1)
            s += __ldg(w + ((oc * 128 + ic) * 3 + j) * 3 + i);
    g_w25[(m * 128 + ic) * 128 + oc] = s;
}

// ================= dconv1 on block-constant input: 9 distinct values per 16x16 block =================
// grid (32 b, 9 vt), 256 thr. vt = ty*3+tx, ty/tx in {top,mid,bot}/{left,mid,right}.
__global__ void dconv1_blocks_kernel(const float* __restrict__ bias) {
    __shared__ float s_y[8192]; // [ic][pos]
    int b = blockIdx.x, vt = blockIdx.y;
    int tid = threadIdx.x;
    for (int e = tid; e < 8192; e += 256) s_y[e] = g_y[b * 8192 + e];
    __syncthreads();

    int lane = tid & 31;
    int ocb = (tid >> 5) * 16;
    int ty = vt / 3, tx = vt - ty * 3;

    int nyp, ys[2], ydy[2];
    if (ty == 0)      { nyp = 2; ys[0] = 0; ydy[0] = -1; ys[1] = 3; ydy[1] = 0; }
    else if (ty == 1) { nyp = 1; ys[0] = 4; ydy[0] = 0;  ys[1] = 0; ydy[1] = 0; }
    else              { nyp = 2; ys[0] = 2; ydy[0] = 0;  ys[1] = 1; ydy[1] = 1; }
    int nxp, xs[2], xdx[2];
    if (tx == 0)      { nxp = 2; xs[0] = 0; xdx[0] = -1; xs[1] = 3; xdx[1] = 0; }
    else if (tx == 1) { nxp = 1; xs[0] = 4; xdx[0] = 0;  xs[1] = 0; xdx[1] = 0; }
    else              { nxp = 2; xs[0] = 2; xdx[0] = 0;  xs[1] = 1; xdx[1] = 1; }

    float acc0[16], acc1[16];
#pragma unroll
    for (int i = 0; i < 16; i++) { acc0[i] = __ldg(bias + ocb + i); acc1[i] = acc0[i]; }

    int pos0 = lane, pos1 = lane + 32;
    int gy0 = pos0 >> 3, gx0 = pos0 & 7;
    int gy1 = pos1 >> 3, gx1 = pos1 & 7;

    for (int a = 0; a < nyp; a++) {
        for (int c = 0; c < nxp; c++) {
            int m = ys[a] * 5 + xs[c];
            int dy = ydy[a], dx = xdx[c];
            int ny0 = gy0 + dy, nx0 = gx0 + dx;
            int ny1 = gy1 + dy, nx1 = gx1 + dx;
            bool v0 = ((unsigned)ny0 < 8u) && ((unsigned)nx0 < 8u);
            bool v1 = ((unsigned)ny1 < 8u) && ((unsigned)nx1 < 8u);
            int np0 = ny0 * 8 + nx0, np1 = ny1 * 8 + nx1;
            const float* wbase = g_w25 + (m * 128) * 128 + ocb;
#pragma unroll 4
            for (int ic = 0; ic < 128; ic++) {
                float yv0 = v0 ? s_y[ic * 64 + np0] : 0.f;
                float yv1 = v1 ? s_y[ic * 64 + np1] : 0.f;
                const float* wp = wbase + ic * 128;
#pragma unroll
                for (int q = 0; q < 4; q++) {
                    float4 wv = __ldg((const float4*)wp + q);
                    acc0[q * 4 + 0] += wv.x * yv0; acc1[q * 4 + 0] += wv.x * yv1;
                    acc0[q * 4 + 1] += wv.y * yv0; acc1[q * 4 + 1] += wv.y * yv1;
                    acc0[q * 4 + 2] += wv.z * yv0; acc1[q * 4 + 2] += wv.z * yv1;
                    acc0[q * 4 + 3] += wv.w * yv0; acc1[q * 4 + 3] += wv.w * yv1;
                }
            }
        }
    }
    float* op = g_r9 + ((size_t)(b * 9 + vt) * 128 + ocb) * 64;
#pragma unroll
    for (int i = 0; i < 16; i++) {
        op[i * 64 + pos0] = fmaxf(acc0[i], 0.f);
        op[i * 64 + pos1] = fmaxf(acc1[i], 0.f);
    }
}

// ================= dconv2 1x1 (128->3) on 9 block values + scatter to full image =================
// grid (64 pos, 32 b), 128 thr
__global__ void dconv2_scatter_kernel(const float* __restrict__ w,
                                      const float* __restrict__ bias,
                                      float* __restrict__ xhat) {
    __shared__ float s_r[1152]; // [vt][oc]
    __shared__ float s_v[27];   // [vt][co]
    int pos = blockIdx.x, b = blockIdx.y;
    int tid = threadIdx.x;
    for (int e = tid; e < 1152; e += 128) {
        int vt = e >> 7, oc = e & 127;
        s_r[e] = g_r9[((size_t)(b * 9 + vt) * 128 + oc) * 64 + pos];
    }
    __syncthreads();
    if (tid < 27) {
        int vt = tid / 3, co = tid - vt * 3;
        float acc = __ldg(bias + co);
        const float* wr = w + co * 128;
        const float* rr = s_r + vt * 128;
#pragma unroll 8
        for (int oc = 0; oc < 128; oc++) acc += __ldg(wr + oc) * rr[oc];
        s_v[tid] = acc;
    }
    __syncthreads();
    int gy = pos >> 3, gx = pos & 7;
    for (int pp = tid; pp < 256; pp += 128) {
        int ly = pp >> 4, lx = pp & 15;
        int ty2 = (ly == 0) ? 0 : ((ly == 15) ? 2 : 1);
        int tx2 = (lx == 0) ? 0 : ((lx == 15) ? 2 : 1);
        int vtp = ty2 * 3 + tx2;
        int py = gy * 16 + ly, px = gx * 16 + lx;
#pragma unroll
        for (int co = 0; co < 3; co++)
            xhat[((b * 3 + co) * 128 + py) * 128 + px] = s_v[vtp * 3 + co];
    }
}

// ================= launch =================
extern "C" void kernel_launch(void* const* d_in, const int* in_sizes, int n_in,
                              void* d_out, int out_size) {
    const float* x   = (const float*)d_in[0];
    const float* ew1 = (const float*)d_in[1];
    const float* eb1 = (const float*)d_in[2];
    const float* ew2 = (const float*)d_in[3];
    const float* eb2 = (const float*)d_in[4];
    const float* pw  = (const float*)d_in[5];
    const float* pb  = (const float*)d_in[6];
    const float* cb  = (const float*)d_in[7];
    const float* dpw = (const float*)d_in[8];
    const float* dpb = (const float*)d_in[9];
    const float* dw1 = (const float*)d_in[10];
    const float* db1 = (const float*)d_in[11];
    const float* dw2 = (const float*)d_in[12];
    const float* db2 = (const float*)d_in[13];

    float* out   = (float*)d_out;
    float* xhat  = out;               // 32*3*128*128 = 1572864
    float* idxo  = out + 1572864;     // 32*8*8       = 2048
    float* losso = out + 1574912;     // 1
    float* zeo   = out + 1574913;     // 32*64*8*8    = 131072

    // input-independent kernels first (also shifts ncu's fixed capture ordinal
    // onto a heavy kernel instead of zero_loss)
    zero_loss_kernel<<<1, 1>>>();
    w25_kernel<<<1600, 256>>>(dw1);
    enc1_kernel<<<dim3(64, 32), 256>>>(x, ew1, eb1);
    enc2_pool_kernel<<<dim3(32, 4, 8), 128>>>(ew2, eb2);
    proj_kernel<<<32, 256>>>(pw, pb, zeo);
    vq_kernel<<<2048, 128>>>(zeo, cb, idxo);
    finalize_loss_kernel<<<1, 1>>>(losso);
    dproj_kernel<<<32, 256>>>(cb, dpw, dpb);
    dconv1_blocks_kernel<<<dim3(32, 9), 256>>>(db1);
    dconv2_scatter_kernel<<<dim3(64, 32), 128>>>(dw2, db2, xhat);
}

// round 5
// speedup vs baseline: 2.1203x; 1.3832x over previous
#include <cuda_runtime.h>

// ---------------- problem constants ----------------
// x:(32,3,128,128)  enc1->(32,128,64,64)  enc2->(32,128,32,32) pool->(32,128,8,8)
// proj-> z_e (32,64,8,8)  VQ K=512,D=64  dproj->(32,128,8,8) up x16 -> dconv1 -> dconv2 -> (32,3,128,128)

// ---------------- device scratch (no allocations allowed) ----------------
__device__ float g_h1[32 * 128 * 64 * 64];    // encoder conv1 output (64 MB)
__device__ float g_hp[32 * 128 * 8 * 8];      // pooled encoder features
__device__ float g_y [32 * 128 * 8 * 8];      // dproj output (relu'd)
__device__ float g_r9[32 * 9 * 128 * 64];     // dconv1: 9 distinct values per 16x16 block
__device__ float g_w25[25 * 128 * 128];       // pre-summed dconv1 weight subsets [m][ic][oc]
__device__ float g_w2t[128 * 9 * 128];        // enc2 weights transposed: [ic][tap][oc]
__device__ int   g_idx[2048];
__device__ float g_loss;

// ================= enc2 weight transpose: w[oc][ic][ky][kx] -> g_w2t[ic][tap][oc] =================
__global__ void w2t_kernel(const float* __restrict__ w) {
    int e = blockIdx.x * 256 + threadIdx.x;   // 147456 elements
    if (e >= 147456) return;
    int oc = e & 127; int t = e >> 7;         // t = ic*9 + tap
    int tap = t % 9; int icf = t / 9;
    g_w2t[e] = __ldg(w + (oc * 128 + icf) * 9 + tap);
}

// ================= encoder conv1: 3->128, 3x3, stride 2, pad 1, relu =================
// grid (64 oy, 32 b), 256 thr: ox = tid&63, ocg = tid>>6 (4 groups of 32 oc)
__global__ void enc1_kernel(const float* __restrict__ x,
                            const float* __restrict__ w,
                            const float* __restrict__ bias) {
    __shared__ float ws[3456]; // [c][ky][kx][128]
    int oy = blockIdx.x, b = blockIdx.y;
    int tid = threadIdx.x;
    for (int e = tid; e < 3456; e += 256) {
        int oc = e & 127; int t = e >> 7;
        int c = t / 9; int r = t - c * 9; int ky = r / 3, kx = r - ky * 3;
        ws[e] = w[((oc * 3 + c) * 3 + ky) * 3 + kx];
    }
    __syncthreads();
    int ox = tid & 63, ocg = tid >> 6;
    float acc[32];
#pragma unroll
    for (int i = 0; i < 32; i++) acc[i] = __ldg(bias + ocg * 32 + i);
    const float* xb = x + b * 3 * 128 * 128;
#pragma unroll
    for (int c = 0; c < 3; c++) {
#pragma unroll
        for (int ky = 0; ky < 3; ky++) {
            int iy = 2 * oy + ky - 1;
#pragma unroll
            for (int kx = 0; kx < 3; kx++) {
                int ix = 2 * ox + kx - 1;
                float xv = 0.f;
                if ((unsigned)iy < 128u && (unsigned)ix < 128u)
                    xv = __ldg(xb + (c * 128 + iy) * 128 + ix);
                const float* wp = &ws[((c * 3 + ky) * 3 + kx) * 128 + ocg * 32];
#pragma unroll
                for (int q = 0; q < 8; q++) {
                    float4 wv = *(const float4*)(wp + q * 4);
                    acc[q * 4 + 0] += wv.x * xv;
                    acc[q * 4 + 1] += wv.y * xv;
                    acc[q * 4 + 2] += wv.z * xv;
                    acc[q * 4 + 3] += wv.w * xv;
                }
            }
        }
    }
    float* op = g_h1 + ((b * 128 + ocg * 32) * 64 + oy) * 64 + ox;
#pragma unroll
    for (int i = 0; i < 32; i++) op[i * 64 * 64] = fmaxf(acc[i], 0.f);
}

// ================= encoder conv2 (128->128, 3x3, s2, p1) + relu + 4x4 avg pool (fused) =================
// Even/odd de-strided smem: per (ic,ky) inputs = 2 aligned LDS.128 + 1 scalar; weights broadcast.
// grid (32 b, 2 ocg, 8 gy), 256 thr; block tile = 64 oc x (4 rows x 32 cols).
// Thread: ocq = tid>>5 (8 oc), lane: r = (lane>>3) out row, cg = lane&7 -> cols 4cg..4cg+3.
__global__ void __launch_bounds__(256) enc2_pool_kernel(const float* __restrict__ bias) {
    __shared__ float sm[9504];
    float* s_in = sm;         // 8 ic * (9 rows * 68): per row E[0..31] @ +0, O[0..32] @ +32
    float* s_w  = sm + 4896;  // 8 ic * 9 tap * 64 oc
    int b = blockIdx.x, ocg = blockIdx.y, gy = blockIdx.z;
    int tid = threadIdx.x;
    int lane = tid & 31;
    int ocq  = tid >> 5;
    int r    = lane >> 3;     // out row 0..3
    int cg   = lane & 7;      // col group (4 cols)

    float acc[8][4];
#pragma unroll
    for (int i = 0; i < 8; i++) {
        float bv = __ldg(bias + ocg * 64 + ocq * 8 + i);
#pragma unroll
        for (int p = 0; p < 4; p++) acc[i][p] = bv;
    }

    for (int ch = 0; ch < 16; ch++) {
        __syncthreads();
        // stage input rows [gy*8-1 .. gy*8+7], cols -1..63, split into even/odd arrays
        for (int e = tid; e < 4680; e += 256) {
            int ic = e / 585; int rem = e - ic * 585;
            int rr = rem / 65; int cc = rem - rr * 65;
            int iy = gy * 8 - 1 + rr; int ix = cc - 1;
            float v = 0.f;
            if ((unsigned)iy < 64u && (unsigned)ix < 64u)
                v = g_h1[((b * 128 + ch * 8 + ic) * 64 + iy) * 64 + ix];
            int off = (cc & 1) ? ((cc - 1) >> 1)      // ix even -> E[ix/2]
                               : (32 + (cc >> 1));    // ix odd  -> O[(ix+1)/2]
            s_in[ic * 612 + rr * 68 + off] = v;
        }
        // stage weights (coalesced via g_w2t)
        for (int e = tid; e < 4608; e += 256) {
            int ic = e / 576; int rem = e - ic * 576;
            int tap = rem >> 6; int ocl = rem & 63;
            s_w[e] = g_w2t[((ch * 8 + ic) * 9 + tap) * 128 + ocg * 64 + ocl];
        }
        __syncthreads();
#pragma unroll
        for (int ic = 0; ic < 8; ic++) {
            const float* sib = s_in + ic * 612;
            const float* swb = s_w + ic * 576 + ocq * 8;
#pragma unroll
            for (int ky = 0; ky < 3; ky++) {
                const float* rp = sib + (2 * r + ky) * 68;
                float4 E4 = *(const float4*)(rp + 4 * cg);
                float4 O4 = *(const float4*)(rp + 32 + 4 * cg);
                float  O1 = rp[36 + 4 * cg];
                float in0[4] = {O4.x, O4.y, O4.z, O4.w};   // kx=0
                float in1[4] = {E4.x, E4.y, E4.z, E4.w};   // kx=1
                float in2[4] = {O4.y, O4.z, O4.w, O1};     // kx=2
#pragma unroll
                for (int kx = 0; kx < 3; kx++) {
                    const float* wp = swb + (ky * 3 + kx) * 64;
                    float4 wA = *(const float4*)wp;
                    float4 wB = *(const float4*)(wp + 4);
                    float wr[8] = {wA.x, wA.y, wA.z, wA.w, wB.x, wB.y, wB.z, wB.w};
                    const float* in = (kx == 0) ? in0 : (kx == 1) ? in1 : in2;
#pragma unroll
                    for (int i = 0; i < 8; i++) {
#pragma unroll
                        for (int p = 0; p < 4; p++) acc[i][p] += wr[i] * in[p];
                    }
                }
            }
        }
    }
    // epilogue: relu, sum 4 cols in regs, sum 4 rows via shfl (rows live in lane bits 3..4)
#pragma unroll
    for (int i = 0; i < 8; i++) {
        float s = fmaxf(acc[i][0], 0.f) + fmaxf(acc[i][1], 0.f)
                + fmaxf(acc[i][2], 0.f) + fmaxf(acc[i][3], 0.f);
        s += __shfl_xor_sync(0xffffffffu, s, 8);
        s += __shfl_xor_sync(0xffffffffu, s, 16);
        if (r == 0)
            g_hp[((b * 128 + ocg * 64 + ocq * 8 + i) * 8 + gy) * 8 + cg] = s * (1.f / 16.f);
    }
}

// ================= proj 1x1: 128 -> 64, writes z_e straight into d_out slot =================
__global__ void proj_kernel(const float* __restrict__ w,
                            const float* __restrict__ bias,
                            float* __restrict__ zout) {
    __shared__ float s_hp[8192]; // [hc][pos]
    int b = blockIdx.x, tid = threadIdx.x;
    for (int e = tid; e < 8192; e += 256) s_hp[e] = g_hp[b * 8192 + e];
    __syncthreads();
    int pos = tid & 63, dg = tid >> 6;
    for (int dl = 0; dl < 16; dl++) {
        int d = dg * 16 + dl;
        float acc = __ldg(bias + d);
        const float* wr = w + d * 128;
#pragma unroll 8
        for (int hc = 0; hc < 128; hc++) acc += __ldg(wr + hc) * s_hp[hc * 64 + pos];
        zout[(b * 64 + d) * 64 + pos] = acc;
    }
}

// ================= vector quantizer: smem-tiled, coalesced =================
__global__ void zero_loss_kernel() { g_loss = 0.f; }

// grid 32 (one per image), 512 thr: pos = tid&63, kq = tid>>6 (8 code quarters of 8)
__global__ void __launch_bounds__(512) vq_kernel(const float* __restrict__ z,
                                                 const float* __restrict__ cb,
                                                 float* __restrict__ idx_out) {
    __shared__ float s_z[64 * 68];
    __shared__ float s_c[64 * 68];
    __shared__ float s_rv[512];
    __shared__ int   s_ri[512];
    int b = blockIdx.x, tid = threadIdx.x;
    int pos = tid & 63, kq = tid >> 6;
    for (int e = tid; e < 4096; e += 512) {
        int d = e >> 6, p = e & 63;
        s_z[p * 68 + d] = z[(b * 64 + d) * 64 + p];
    }
    float bestv = 3.4e38f; int besti = 0;
    for (int t = 0; t < 8; t++) {
        __syncthreads();
        for (int e = tid; e < 4096; e += 512) {
            int k = e >> 6, d = e & 63;
            s_c[k * 68 + d] = __ldg(cb + (t * 64 + k) * 64 + d);
        }
        __syncthreads();
        float acc[8];
#pragma unroll
        for (int j = 0; j < 8; j++) acc[j] = 0.f;
        const float* zp = s_z + pos * 68;
        for (int d = 0; d < 64; d += 4) {
            float4 z4 = *(const float4*)(zp + d);
#pragma unroll
            for (int j = 0; j < 8; j++) {
                float4 c4 = *(const float4*)(s_c + (kq * 8 + j) * 68 + d);
                float d0 = c4.x - z4.x; acc[j] += d0 * d0;
                float d1 = c4.y - z4.y; acc[j] += d1 * d1;
                float d2 = c4.z - z4.z; acc[j] += d2 * d2;
                float d3 = c4.w - z4.w; acc[j] += d3 * d3;
            }
        }
#pragma unroll
        for (int j = 0; j < 8; j++) {
            int k = t * 64 + kq * 8 + j;
            if (acc[j] < bestv) { bestv = acc[j]; besti = k; }
        }
    }
    s_rv[tid] = bestv; s_ri[tid] = besti;
    __syncthreads();
    if (tid < 64) {
        float bv = s_rv[tid]; int bi = s_ri[tid];
#pragma unroll
        for (int q = 1; q < 8; q++) {
            float v = s_rv[q * 64 + tid]; int i2 = s_ri[q * 64 + tid];
            if (v < bv || (v == bv && i2 < bi)) { bv = v; bi = i2; }
        }
        int n = b * 64 + tid;
        g_idx[n] = bi;
        idx_out[n] = (float)bi;
        s_rv[tid] = bv;
    }
    __syncthreads();
    if (tid == 0) {
        float s = 0.f;
        for (int i = 0; i < 64; i++) s += s_rv[i];
        atomicAdd(&g_loss, s);
    }
}

__global__ void finalize_loss_kernel(float* __restrict__ out) {
    // vq_loss = (1 + 0.25) * mean((z_q - z_e)^2) ; mean over 2048*64 elements
    out[0] = g_loss * (1.25f / 131072.f);
}

// ================= dproj 1x1: 64 -> 128 on quantized codes, relu (pre-upsample) =================
__global__ void dproj_kernel(const float* __restrict__ cb,
                             const float* __restrict__ w,
                             const float* __restrict__ bias) {
    __shared__ float s_zq[4096]; // [d][pos]
    __shared__ int   s_i[64];
    int b = blockIdx.x, tid = threadIdx.x;
    if (tid < 64) s_i[tid] = g_idx[b * 64 + tid];
    __syncthreads();
    for (int e = tid; e < 4096; e += 256) {
        int d = e >> 6, pos = e & 63;
        s_zq[e] = __ldg(cb + s_i[pos] * 64 + d);
    }
    __syncthreads();
    int pos = tid & 63, hg = tid >> 6;
    for (int h = 0; h < 32; h++) {
        int hc = hg * 32 + h;
        float acc = __ldg(bias + hc);
        const float* wr = w + hc * 64;
#pragma unroll 8
        for (int d = 0; d < 64; d++) acc += __ldg(wr + d) * s_zq[d * 64 + pos];
        g_y[b * 8192 + hc * 64 + pos] = fmaxf(acc, 0.f); // relu(upsample(y)) == upsample(relu(y))
    }
}

// ================= dconv1 weight-subset precompute: 25 matrices [m][ic][oc] =================
__global__ void w25_kernel(const float* __restrict__ w) {
    int g = blockIdx.x * 256 + threadIdx.x;
    if (g >= 25 * 16384) return;
    int m = g >> 14; int r = g & 16383; int ic = r & 127; int oc = r >> 7;
    int sy = m / 5, sx = m - sy * 5;
    const int mask[5] = {1, 4, 3, 6, 7};
    float s = 0.f;
    for (int j = 0; j < 3; j++) if ((mask[sy] >> j) & 1)
        for (int i = 0; i < 3; i++) if ((mask[sx] >> i) & 1)
            s += __ldg(w + ((oc * 128 + ic) * 3 + j) * 3 + i);
    g_w25[(m * 128 + ic) * 128 + oc] = s;
}

// ================= dconv1 on block-constant input: 9 distinct values per 16x16 block =================
__global__ void dconv1_blocks_kernel(const float* __restrict__ bias) {
    __shared__ float s_y[8192]; // [ic][pos]
    int b = blockIdx.x, vt = blockIdx.y;
    int tid = threadIdx.x;
    for (int e = tid; e < 8192; e += 256) s_y[e] = g_y[b * 8192 + e];
    __syncthreads();

    int lane = tid & 31;
    int ocb = (tid >> 5) * 16;
    int ty = vt / 3, tx = vt - ty * 3;

    int nyp, ys[2], ydy[2];
    if (ty == 0)      { nyp = 2; ys[0] = 0; ydy[0] = -1; ys[1] = 3; ydy[1] = 0; }
    else if (ty == 1) { nyp = 1; ys[0] = 4; ydy[0] = 0;  ys[1] = 0; ydy[1] = 0; }
    else              { nyp = 2; ys[0] = 2; ydy[0] = 0;  ys[1] = 1; ydy[1] = 1; }
    int nxp, xs[2], xdx[2];
    if (tx == 0)      { nxp = 2; xs[0] = 0; xdx[0] = -1; xs[1] = 3; xdx[1] = 0; }
    else if (tx == 1) { nxp = 1; xs[0] = 4; xdx[0] = 0;  xs[1] = 0; xdx[1] = 0; }
    else              { nxp = 2; xs[0] = 2; xdx[0] = 0;  xs[1] = 1; xdx[1] = 1; }

    float acc0[16], acc1[16];
#pragma unroll
    for (int i = 0; i < 16; i++) { acc0[i] = __ldg(bias + ocb + i); acc1[i] = acc0[i]; }

    int pos0 = lane, pos1 = lane + 32;
    int gy0 = pos0 >> 3, gx0 = pos0 & 7;
    int gy1 = pos1 >> 3, gx1 = pos1 & 7;

    for (int a = 0; a < nyp; a++) {
        for (int c = 0; c < nxp; c++) {
            int m = ys[a] * 5 + xs[c];
            int dy = ydy[a], dx = xdx[c];
            int ny0 = gy0 + dy, nx0 = gx0 + dx;
            int ny1 = gy1 + dy, nx1 = gx1 + dx;
            bool v0 = ((unsigned)ny0 < 8u) && ((unsigned)nx0 < 8u);
            bool v1 = ((unsigned)ny1 < 8u) && ((unsigned)nx1 < 8u);
            int np0 = ny0 * 8 + nx0, np1 = ny1 * 8 + nx1;
            const float* wbase = g_w25 + (m * 128) * 128 + ocb;
#pragma unroll 4
            for (int ic = 0; ic < 128; ic++) {
                float yv0 = v0 ? s_y[ic * 64 + np0] : 0.f;
                float yv1 = v1 ? s_y[ic * 64 + np1] : 0.f;
                const float* wp = wbase + ic * 128;
#pragma unroll
                for (int q = 0; q < 4; q++) {
                    float4 wv = __ldg((const float4*)wp + q);
                    acc0[q * 4 + 0] += wv.x * yv0; acc1[q * 4 + 0] += wv.x * yv1;
                    acc0[q * 4 + 1] += wv.y * yv0; acc1[q * 4 + 1] += wv.y * yv1;
                    acc0[q * 4 + 2] += wv.z * yv0; acc1[q * 4 + 2] += wv.z * yv1;
                    acc0[q * 4 + 3] += wv.w * yv0; acc1[q * 4 + 3] += wv.w * yv1;
                }
            }
        }
    }
    float* op = g_r9 + ((size_t)(b * 9 + vt) * 128 + ocb) * 64;
#pragma unroll
    for (int i = 0; i < 16; i++) {
        op[i * 64 + pos0] = fmaxf(acc0[i], 0.f);
        op[i * 64 + pos1] = fmaxf(acc1[i], 0.f);
    }
}

// ================= dconv2 1x1 (128->3) on 9 block values + scatter to full image =================
__global__ void dconv2_scatter_kernel(const float* __restrict__ w,
                                      const float* __restrict__ bias,
                                      float* __restrict__ xhat) {
    __shared__ float s_r[1152]; // [vt][oc]
    __shared__ float s_v[27];   // [vt][co]
    int pos = blockIdx.x, b = blockIdx.y;
    int tid = threadIdx.x;
    for (int e = tid; e < 1152; e += 128) {
        int vt = e >> 7, oc = e & 127;
        s_r[e] = g_r9[((size_t)(b * 9 + vt) * 128 + oc) * 64 + pos];
    }
    __syncthreads();
    if (tid < 27) {
        int vt = tid / 3, co = tid - vt * 3;
        float acc = __ldg(bias + co);
        const float* wr = w + co * 128;
        const float* rr = s_r + vt * 128;
#pragma unroll 8
        for (int oc = 0; oc < 128; oc++) acc += __ldg(wr + oc) * rr[oc];
        s_v[tid] = acc;
    }
    __syncthreads();
    int gy = pos >> 3, gx = pos & 7;
    for (int pp = tid; pp < 256; pp += 128) {
        int ly = pp >> 4, lx = pp & 15;
        int ty2 = (ly == 0) ? 0 : ((ly == 15) ? 2 : 1);
        int tx2 = (lx == 0) ? 0 : ((lx == 15) ? 2 : 1);
        int vtp = ty2 * 3 + tx2;
        int py = gy * 16 + ly, px = gx * 16 + lx;
#pragma unroll
        for (int co = 0; co < 3; co++)
            xhat[((b * 3 + co) * 128 + py) * 128 + px] = s_v[vtp * 3 + co];
    }
}

// ================= launch =================
extern "C" void kernel_launch(void* const* d_in, const int* in_sizes, int n_in,
                              void* d_out, int out_size) {
    const float* x   = (const float*)d_in[0];
    const float* ew1 = (const float*)d_in[1];
    const float* eb1 = (const float*)d_in[2];
    const float* ew2 = (const float*)d_in[3];
    const float* eb2 = (const float*)d_in[4];
    const float* pw  = (const float*)d_in[5];
    const float* pb  = (const float*)d_in[6];
    const float* cb  = (const float*)d_in[7];
    const float* dpw = (const float*)d_in[8];
    const float* dpb = (const float*)d_in[9];
    const float* dw1 = (const float*)d_in[10];
    const float* db1 = (const float*)d_in[11];
    const float* dw2 = (const float*)d_in[12];
    const float* db2 = (const float*)d_in[13];

    float* out   = (float*)d_out;
    float* xhat  = out;               // 32*3*128*128 = 1572864
    float* idxo  = out + 1572864;     // 32*8*8       = 2048
    float* losso = out + 1574912;     // 1
    float* zeo   = out + 1574913;     // 32*64*8*8    = 131072

    // order keeps enc2 at the profiled launch ordinal (#4)
    w2t_kernel<<<576, 256>>>(ew2);
    w25_kernel<<<1600, 256>>>(dw1);
    enc1_kernel<<<dim3(64, 32), 256>>>(x, ew1, eb1);
    enc2_pool_kernel<<<dim3(32, 2, 8), 256>>>(eb2);
    zero_loss_kernel<<<1, 1>>>();
    proj_kernel<<<32, 256>>>(pw, pb, zeo);
    vq_kernel<<<32, 512>>>(zeo, cb, idxo);
    finalize_loss_kernel<<<1, 1>>>(losso);
    dproj_kernel<<<32, 256>>>(cb, dpw, dpb);
    dconv1_blocks_kernel<<<dim3(32, 9), 256>>>(db1);
    dconv2_scatter_kernel<<<dim3(64, 32), 128>>>(dw2, db2, xhat);
}

// round 6
// speedup vs baseline: 2.4704x; 1.1651x over previous
#include <cuda_runtime.h>

// ---------------- problem constants ----------------
// x:(32,3,128,128)  enc1->(32,128,64,64)  enc2->(32,128,32,32) pool->(32,128,8,8)
// proj-> z_e (32,64,8,8)  VQ K=512,D=64  dproj->(32,128,8,8) up x16 -> dconv1 -> dconv2 -> (32,3,128,128)

// ---------------- device scratch (no allocations allowed) ----------------
__device__ float g_h1[32 * 128 * 64 * 64];    // encoder conv1 output (64 MB)
__device__ float g_hp[32 * 128 * 8 * 8];      // pooled encoder features
__device__ float g_y [32 * 128 * 8 * 8];      // dproj output (relu'd)
__device__ float g_r9[32 * 9 * 128 * 64];     // dconv1: 9 distinct values per 16x16 block
__device__ float g_w25[25 * 128 * 128];       // pre-summed dconv1 weight subsets [m][ic][oc]
__device__ float g_w2t[128 * 9 * 128];        // enc2 weights transposed: [ic][tap][oc]
__device__ int   g_idx[2048];
__device__ float g_loss_part[32];

// ================= enc2 weight transpose: w[oc][ic][ky][kx] -> g_w2t[ic][tap][oc] =================
__global__ void w2t_kernel(const float* __restrict__ w) {
    int e = blockIdx.x * 256 + threadIdx.x;   // 147456 elements
    if (e >= 147456) return;
    int oc = e & 127; int t = e >> 7;         // t = ic*9 + tap
    int tap = t % 9; int icf = t / 9;
    g_w2t[e] = __ldg(w + (oc * 128 + icf) * 9 + tap);
}

// ================= encoder conv1: 3->128, 3x3, stride 2, pad 1, relu =================
// grid (64 oy, 32 b), 256 thr: ox = tid&63, ocg = tid>>6 (4 groups of 32 oc)
__global__ void enc1_kernel(const float* __restrict__ x,
                            const float* __restrict__ w,
                            const float* __restrict__ bias) {
    __shared__ float ws[3456]; // [c][ky][kx][128]
    int oy = blockIdx.x, b = blockIdx.y;
    int tid = threadIdx.x;
    for (int e = tid; e < 3456; e += 256) {
        int oc = e & 127; int t = e >> 7;
        int c = t / 9; int r = t - c * 9; int ky = r / 3, kx = r - ky * 3;
        ws[e] = w[((oc * 3 + c) * 3 + ky) * 3 + kx];
    }
    __syncthreads();
    int ox = tid & 63, ocg = tid >> 6;
    float acc[32];
#pragma unroll
    for (int i = 0; i < 32; i++) acc[i] = __ldg(bias + ocg * 32 + i);
    const float* xb = x + b * 3 * 128 * 128;
#pragma unroll
    for (int c = 0; c < 3; c++) {
#pragma unroll
        for (int ky = 0; ky < 3; ky++) {
            int iy = 2 * oy + ky - 1;
#pragma unroll
            for (int kx = 0; kx < 3; kx++) {
                int ix = 2 * ox + kx - 1;
                float xv = 0.f;
                if ((unsigned)iy < 128u && (unsigned)ix < 128u)
                    xv = __ldg(xb + (c * 128 + iy) * 128 + ix);
                const float* wp = &ws[((c * 3 + ky) * 3 + kx) * 128 + ocg * 32];
#pragma unroll
                for (int q = 0; q < 8; q++) {
                    float4 wv = *(const float4*)(wp + q * 4);
                    acc[q * 4 + 0] += wv.x * xv;
                    acc[q * 4 + 1] += wv.y * xv;
                    acc[q * 4 + 2] += wv.z * xv;
                    acc[q * 4 + 3] += wv.w * xv;
                }
            }
        }
    }
    float* op = g_h1 + ((b * 128 + ocg * 32) * 64 + oy) * 64 + ox;
#pragma unroll
    for (int i = 0; i < 32; i++) op[i * 64 * 64] = fmaxf(acc[i], 0.f);
}

// ================= encoder conv2 (128->128, 3x3, s2, p1) + relu + 4x4 avg pool (fused) =================
// Even/odd de-strided smem; division-free staging; 4 blocks/SM forced.
// grid (32 b, 2 ocg, 8 gy), 256 thr; block tile = 64 oc x (4 rows x 32 cols).
__global__ void __launch_bounds__(256, 4) enc2_pool_kernel(const float* __restrict__ bias) {
    __shared__ float sm[9504];
    float* s_in = sm;         // 8 ic * (9 rows * 68): per row E[0..31] @ +0, O[0..32] @ +32
    float* s_w  = sm + 4896;  // 8 ic * 9 tap * 64 oc
    int b = blockIdx.x, ocg = blockIdx.y, gy = blockIdx.z;
    int tid = threadIdx.x;
    int lane = tid & 31;
    int ocq  = tid >> 5;
    int r    = lane >> 3;     // out row 0..3
    int cg   = lane & 7;      // col group (4 cols)

    // staging decomposition (division-free): icS = tid>>5, 32 lanes cover cols
    int icS = tid >> 5;
    int off0 = (lane & 1) ? ((lane - 1) >> 1) : (32 + (lane >> 1));           // cc = lane
    int off1 = (lane & 1) ? ((lane + 31) >> 1) : (32 + ((lane + 32) >> 1));   // cc = lane+32

    float acc[8][4];
#pragma unroll
    for (int i = 0; i < 8; i++) {
        float bv = __ldg(bias + ocg * 64 + ocq * 8 + i);
#pragma unroll
        for (int p = 0; p < 4; p++) acc[i][p] = bv;
    }

    for (int ch = 0; ch < 16; ch++) {
        __syncthreads();
        // ---- stage inputs: rows gy*8-1..gy*8+7, cols -1..63 split even/odd ----
        {
            const float* src = g_h1 + (((size_t)b * 128 + ch * 8 + icS) * 64) * 64;
            float* dst = s_in + icS * 612;
            int iy0 = gy * 8 - 1;
#pragma unroll
            for (int rr = 0; rr < 9; rr++) {
                int iy = iy0 + rr;
                bool rowok = (unsigned)iy < 64u;
                const float* srow = src + iy * 64;
                // cc = lane  -> ix = lane-1
                {
                    int ix = lane - 1;
                    float v = (rowok && (unsigned)ix < 64u) ? srow[ix] : 0.f;
                    dst[rr * 68 + off0] = v;
                }
                // cc = lane+32 -> ix = lane+31
                {
                    int ix = lane + 31;
                    float v = (rowok && ix < 64) ? srow[ix] : 0.f;
                    dst[rr * 68 + off1] = v;
                }
            }
            // cc = 64 -> ix = 63, one per row, lanes 0..8 of icS group
            if (lane < 9) {
                int iy = iy0 + lane;
                float v = ((unsigned)iy < 64u) ? src[iy * 64 + 63] : 0.f;
                dst[lane * 68 + 64] = v;
            }
        }
        // ---- stage weights (pure shift/mask indexing) ----
        {
            const float* wsrc = g_w2t + (size_t)ch * 72 * 128 + ocg * 64;
#pragma unroll
            for (int k = 0; k < 18; k++) {
                int e = k * 256 + tid;
                int rowi = e >> 6, ocl = e & 63;
                s_w[e] = wsrc[rowi * 128 + ocl];
            }
        }
        __syncthreads();
#pragma unroll
        for (int ic = 0; ic < 8; ic++) {
            const float* sib = s_in + ic * 612;
            const float* swb = s_w + ic * 576 + ocq * 8;
#pragma unroll
            for (int ky = 0; ky < 3; ky++) {
                const float* rp = sib + (2 * r + ky) * 68;
                float4 E4 = *(const float4*)(rp + 4 * cg);
                float4 O4 = *(const float4*)(rp + 32 + 4 * cg);
                float  O1 = rp[36 + 4 * cg];
                float in0[4] = {O4.x, O4.y, O4.z, O4.w};   // kx=0
                float in1[4] = {E4.x, E4.y, E4.z, E4.w};   // kx=1
                float in2[4] = {O4.y, O4.z, O4.w, O1};     // kx=2
#pragma unroll
                for (int kx = 0; kx < 3; kx++) {
                    const float* wp = swb + (ky * 3 + kx) * 64;
                    float4 wA = *(const float4*)wp;
                    float4 wB = *(const float4*)(wp + 4);
                    float wr[8] = {wA.x, wA.y, wA.z, wA.w, wB.x, wB.y, wB.z, wB.w};
                    const float* in = (kx == 0) ? in0 : (kx == 1) ? in1 : in2;
#pragma unroll
                    for (int i = 0; i < 8; i++) {
#pragma unroll
                        for (int p = 0; p < 4; p++) acc[i][p] += wr[i] * in[p];
                    }
                }
            }
        }
    }
    // epilogue: relu, sum 4 cols in regs, sum 4 rows via shfl (rows live in lane bits 3..4)
#pragma unroll
    for (int i = 0; i < 8; i++) {
        float s = fmaxf(acc[i][0], 0.f) + fmaxf(acc[i][1], 0.f)
                + fmaxf(acc[i][2], 0.f) + fmaxf(acc[i][3], 0.f);
        s += __shfl_xor_sync(0xffffffffu, s, 8);
        s += __shfl_xor_sync(0xffffffffu, s, 16);
        if (r == 0)
            g_hp[((b * 128 + ocg * 64 + ocq * 8 + i) * 8 + gy) * 8 + cg] = s * (1.f / 16.f);
    }
}

// ================= proj 1x1: 128 -> 64, writes z_e straight into d_out slot =================
__global__ void proj_kernel(const float* __restrict__ w,
                            const float* __restrict__ bias,
                            float* __restrict__ zout) {
    __shared__ float s_hp[8192]; // [hc][pos]
    int b = blockIdx.x, tid = threadIdx.x;
    for (int e = tid; e < 8192; e += 256) s_hp[e] = g_hp[b * 8192 + e];
    __syncthreads();
    int pos = tid & 63, dg = tid >> 6;
    for (int dl = 0; dl < 16; dl++) {
        int d = dg * 16 + dl;
        float acc = __ldg(bias + d);
        const float* wr = w + d * 128;
#pragma unroll 8
        for (int hc = 0; hc < 128; hc++) acc += __ldg(wr + hc) * s_hp[hc * 64 + pos];
        zout[(b * 64 + d) * 64 + pos] = acc;
    }
}

// ================= vector quantizer: smem-tiled, coalesced, per-image loss partial =================
// grid 32 (one per image), 512 thr: pos = tid&63, kq = tid>>6 (8 code quarters of 8)
__global__ void __launch_bounds__(512) vq_kernel(const float* __restrict__ z,
                                                 const float* __restrict__ cb,
                                                 float* __restrict__ idx_out) {
    __shared__ float s_z[64 * 68];
    __shared__ float s_c[64 * 68];
    __shared__ float s_rv[512];
    __shared__ int   s_ri[512];
    int b = blockIdx.x, tid = threadIdx.x;
    int pos = tid & 63, kq = tid >> 6;
    for (int e = tid; e < 4096; e += 512) {
        int d = e >> 6, p = e & 63;
        s_z[p * 68 + d] = z[(b * 64 + d) * 64 + p];
    }
    float bestv = 3.4e38f; int besti = 0;
    for (int t = 0; t < 8; t++) {
        __syncthreads();
        for (int e = tid; e < 4096; e += 512) {
            int k = e >> 6, d = e & 63;
            s_c[k * 68 + d] = __ldg(cb + (t * 64 + k) * 64 + d);
        }
        __syncthreads();
        float acc[8];
#pragma unroll
        for (int j = 0; j < 8; j++) acc[j] = 0.f;
        const float* zp = s_z + pos * 68;
        for (int d = 0; d < 64; d += 4) {
            float4 z4 = *(const float4*)(zp + d);
#pragma unroll
            for (int j = 0; j < 8; j++) {
                float4 c4 = *(const float4*)(s_c + (kq * 8 + j) * 68 + d);
                float d0 = c4.x - z4.x; acc[j] += d0 * d0;
                float d1 = c4.y - z4.y; acc[j] += d1 * d1;
                float d2 = c4.z - z4.z; acc[j] += d2 * d2;
                float d3 = c4.w - z4.w; acc[j] += d3 * d3;
            }
        }
#pragma unroll
        for (int j = 0; j < 8; j++) {
            int k = t * 64 + kq * 8 + j;
            if (acc[j] < bestv) { bestv = acc[j]; besti = k; }
        }
    }
    s_rv[tid] = bestv; s_ri[tid] = besti;
    __syncthreads();
    if (tid < 64) {
        float bv = s_rv[tid]; int bi = s_ri[tid];
#pragma unroll
        for (int q = 1; q < 8; q++) {
            float v = s_rv[q * 64 + tid]; int i2 = s_ri[q * 64 + tid];
            if (v < bv || (v == bv && i2 < bi)) { bv = v; bi = i2; }
        }
        int n = b * 64 + tid;
        g_idx[n] = bi;
        idx_out[n] = (float)bi;
        s_rv[tid] = bv;
    }
    __syncthreads();
    if (tid == 0) {
        float s = 0.f;
        for (int i = 0; i < 64; i++) s += s_rv[i];
        g_loss_part[b] = s;
    }
}

__global__ void finalize_loss_kernel(float* __restrict__ out) {
    // vq_loss = (1 + 0.25) * mean((z_q - z_e)^2) ; mean over 2048*64 elements
    float s = 0.f;
    for (int i = 0; i < 32; i++) s += g_loss_part[i];
    out[0] = s * (1.25f / 131072.f);
}

// ================= dproj 1x1: 64 -> 128 on quantized codes, relu (pre-upsample) =================
__global__ void dproj_kernel(const float* __restrict__ cb,
                             const float* __restrict__ w,
                             const float* __restrict__ bias) {
    __shared__ float s_zq[4096]; // [d][pos]
    __shared__ int   s_i[64];
    int b = blockIdx.x, tid = threadIdx.x;
    if (tid < 64) s_i[tid] = g_idx[b * 64 + tid];
    __syncthreads();
    for (int e = tid; e < 4096; e += 256) {
        int d = e >> 6, pos = e & 63;
        s_zq[e] = __ldg(cb + s_i[pos] * 64 + d);
    }
    __syncthreads();
    int pos = tid & 63, hg = tid >> 6;
    for (int h = 0; h < 32; h++) {
        int hc = hg * 32 + h;
        float acc = __ldg(bias + hc);
        const float* wr = w + hc * 64;
#pragma unroll 8
        for (int d = 0; d < 64; d++) acc += __ldg(wr + d) * s_zq[d * 64 + pos];
        g_y[b * 8192 + hc * 64 + pos] = fmaxf(acc, 0.f); // relu(upsample(y)) == upsample(relu(y))
    }
}

// ================= dconv1 weight-subset precompute: 25 matrices [m][ic][oc] =================
__global__ void w25_kernel(const float* __restrict__ w) {
    int g = blockIdx.x * 256 + threadIdx.x;
    if (g >= 25 * 16384) return;
    int m = g >> 14; int r = g & 16383; int ic = r & 127; int oc = r >> 7;
    int sy = m / 5, sx = m - sy * 5;
    const int mask[5] = {1, 4, 3, 6, 7};
    float s = 0.f;
    for (int j = 0; j < 3; j++) if ((mask[sy] >> j) & 1)
        for (int i = 0; i < 3; i++) if ((mask[sx] >> i) & 1)
            s += __ldg(w + ((oc * 128 + ic) * 3 + j) * 3 + i);
    g_w25[(m * 128 + ic) * 128 + oc] = s;
}

// ================= dconv1 on block-constant input: 9 distinct values per 16x16 block =================
__global__ void dconv1_blocks_kernel(const float* __restrict__ bias) {
    __shared__ float s_y[8192]; // [ic][pos]
    int b = blockIdx.x, vt = blockIdx.y;
    int tid = threadIdx.x;
    for (int e = tid; e < 8192; e += 256) s_y[e] = g_y[b * 8192 + e];
    __syncthreads();

    int lane = tid & 31;
    int ocb = (tid >> 5) * 16;
    int ty = vt / 3, tx = vt - ty * 3;

    int nyp, ys[2], ydy[2];
    if (ty == 0)      { nyp = 2; ys[0] = 0; ydy[0] = -1; ys[1] = 3; ydy[1] = 0; }
    else if (ty == 1) { nyp = 1; ys[0] = 4; ydy[0] = 0;  ys[1] = 0; ydy[1] = 0; }
    else              { nyp = 2; ys[0] = 2; ydy[0] = 0;  ys[1] = 1; ydy[1] = 1; }
    int nxp, xs[2], xdx[2];
    if (tx == 0)      { nxp = 2; xs[0] = 0; xdx[0] = -1; xs[1] = 3; xdx[1] = 0; }
    else if (tx == 1) { nxp = 1; xs[0] = 4; xdx[0] = 0;  xs[1] = 0; xdx[1] = 0; }
    else              { nxp = 2; xs[0] = 2; xdx[0] = 0;  xs[1] = 1; xdx[1] = 1; }

    float acc0[16], acc1[16];
#pragma unroll
    for (int i = 0; i < 16; i++) { acc0[i] = __ldg(bias + ocb + i); acc1[i] = acc0[i]; }

    int pos0 = lane, pos1 = lane + 32;
    int gy0 = pos0 >> 3, gx0 = pos0 & 7;
    int gy1 = pos1 >> 3, gx1 = pos1 & 7;

    for (int a = 0; a < nyp; a++) {
        for (int c = 0; c < nxp; c++) {
            int m = ys[a] * 5 + xs[c];
            int dy = ydy[a], dx = xdx[c];
            int ny0 = gy0 + dy, nx0 = gx0 + dx;
            int ny1 = gy1 + dy, nx1 = gx1 + dx;
            bool v0 = ((unsigned)ny0 < 8u) && ((unsigned)nx0 < 8u);
            bool v1 = ((unsigned)ny1 < 8u) && ((unsigned)nx1 < 8u);
            int np0 = ny0 * 8 + nx0, np1 = ny1 * 8 + nx1;
            const float* wbase = g_w25 + (m * 128) * 128 + ocb;
#pragma unroll 4
            for (int ic = 0; ic < 128; ic++) {
                float yv0 = v0 ? s_y[ic * 64 + np0] : 0.f;
                float yv1 = v1 ? s_y[ic * 64 + np1] : 0.f;
                const float* wp = wbase + ic * 128;
#pragma unroll
                for (int q = 0; q < 4; q++) {
                    float4 wv = __ldg((const float4*)wp + q);
                    acc0[q * 4 + 0] += wv.x * yv0; acc1[q * 4 + 0] += wv.x * yv1;
                    acc0[q * 4 + 1] += wv.y * yv0; acc1[q * 4 + 1] += wv.y * yv1;
                    acc0[q * 4 + 2] += wv.z * yv0; acc1[q * 4 + 2] += wv.z * yv1;
                    acc0[q * 4 + 3] += wv.w * yv0; acc1[q * 4 + 3] += wv.w * yv1;
                }
            }
        }
    }
    float* op = g_r9 + ((size_t)(b * 9 + vt) * 128 + ocb) * 64;
#pragma unroll
    for (int i = 0; i < 16; i++) {
        op[i * 64 + pos0] = fmaxf(acc0[i], 0.f);
        op[i * 64 + pos1] = fmaxf(acc1[i], 0.f);
    }
}

// ================= dconv2 1x1 (128->3) on 9 block values + scatter to full image =================
__global__ void dconv2_scatter_kernel(const float* __restrict__ w,
                                      const float* __restrict__ bias,
                                      float* __restrict__ xhat) {
    __shared__ float s_r[1152]; // [vt][oc]
    __shared__ float s_v[27];   // [vt][co]
    int pos = blockIdx.x, b = blockIdx.y;
    int tid = threadIdx.x;
    for (int e = tid; e < 1152; e += 128) {
        int vt = e >> 7, oc = e & 127;
        s_r[e] = g_r9[((size_t)(b * 9 + vt) * 128 + oc) * 64 + pos];
    }
    __syncthreads();
    if (tid < 27) {
        int vt = tid / 3, co = tid - vt * 3;
        float acc = __ldg(bias + co);
        const float* wr = w + co * 128;
        const float* rr = s_r + vt * 128;
#pragma unroll 8
        for (int oc = 0; oc < 128; oc++) acc += __ldg(wr + oc) * rr[oc];
        s_v[tid] = acc;
    }
    __syncthreads();
    int gy = pos >> 3, gx = pos & 7;
    for (int pp = tid; pp < 256; pp += 128) {
        int ly = pp >> 4, lx = pp & 15;
        int ty2 = (ly == 0) ? 0 : ((ly == 15) ? 2 : 1);
        int tx2 = (lx == 0) ? 0 : ((lx == 15) ? 2 : 1);
        int vtp = ty2 * 3 + tx2;
        int py = gy * 16 + ly, px = gx * 16 + lx;
#pragma unroll
        for (int co = 0; co < 3; co++)
            xhat[((b * 3 + co) * 128 + py) * 128 + px] = s_v[vtp * 3 + co];
    }
}

// ================= launch =================
extern "C" void kernel_launch(void* const* d_in, const int* in_sizes, int n_in,
                              void* d_out, int out_size) {
    const float* x   = (const float*)d_in[0];
    const float* ew1 = (const float*)d_in[1];
    const float* eb1 = (const float*)d_in[2];
    const float* ew2 = (const float*)d_in[3];
    const float* eb2 = (const float*)d_in[4];
    const float* pw  = (const float*)d_in[5];
    const float* pb  = (const float*)d_in[6];
    const float* cb  = (const float*)d_in[7];
    const float* dpw = (const float*)d_in[8];
    const float* dpb = (const float*)d_in[9];
    const float* dw1 = (const float*)d_in[10];
    const float* db1 = (const float*)d_in[11];
    const float* dw2 = (const float*)d_in[12];
    const float* db2 = (const float*)d_in[13];

    float* out   = (float*)d_out;
    float* xhat  = out;               // 32*3*128*128 = 1572864
    float* idxo  = out + 1572864;     // 32*8*8       = 2048
    float* losso = out + 1574912;     // 1
    float* zeo   = out + 1574913;     // 32*64*8*8    = 131072

    // order keeps enc2 at the profiled launch ordinal (#4)
    w2t_kernel<<<576, 256>>>(ew2);
    w25_kernel<<<1600, 256>>>(dw1);
    enc1_kernel<<<dim3(64, 32), 256>>>(x, ew1, eb1);
    enc2_pool_kernel<<<dim3(32, 2, 8), 256>>>(eb2);
    proj_kernel<<<32, 256>>>(pw, pb, zeo);
    vq_kernel<<<32, 512>>>(zeo, cb, idxo);
    finalize_loss_kernel<<<1, 1>>>(losso);
    dproj_kernel<<<32, 256>>>(cb, dpw, dpb);
    dconv1_blocks_kernel<<<dim3(32, 9), 256>>>(db1);
    dconv2_scatter_kernel<<<dim3(64, 32), 128>>>(dw2, db2, xhat);
}

// round 8
// speedup vs baseline: 2.6229x; 1.0617x over previous
#include <cuda_runtime.h>

// ---------------- problem constants ----------------
// x:(32,3,128,128)  enc1->(32,128,64,64)  enc2->(32,128,32,32) pool->(32,128,8,8)
// proj-> z_e (32,64,8,8)  VQ K=512,D=64  dproj->(32,128,8,8) up x16 -> dconv1 -> dconv2 -> (32,3,128,128)

// ---------------- device scratch (no allocations allowed) ----------------
__device__ float g_h1[32 * 128 * 64 * 64];    // encoder conv1 output (64 MB)
__device__ float g_p2[32 * 2 * 2 * 8 * 64 * 128]; // enc2 split-K partials (67 MB)
__device__ float g_hp[32 * 128 * 8 * 8];      // pooled encoder features
__device__ float g_y [32 * 128 * 8 * 8];      // dproj output (relu'd)
__device__ float g_r9[32 * 9 * 128 * 64];     // dconv1: 9 distinct values per 16x16 block
__device__ float g_w25[25 * 128 * 128];       // pre-summed dconv1 weight subsets [m][ic][oc]
__device__ float g_w2t[128 * 9 * 128];        // enc2 weights transposed: [ic][tap][oc]
__device__ int   g_idx[2048];
__device__ float g_loss_part[32];

// ================= enc2 weight transpose: w[oc][ic][ky][kx] -> g_w2t[ic][tap][oc] =================
__global__ void w2t_kernel(const float* __restrict__ w) {
    int e = blockIdx.x * 256 + threadIdx.x;   // 147456 elements
    if (e >= 147456) return;
    int oc = e & 127; int t = e >> 7;         // t = ic*9 + tap
    int tap = t % 9; int icf = t / 9;
    g_w2t[e] = __ldg(w + (oc * 128 + icf) * 9 + tap);
}

// ================= encoder conv1: 3->128, 3x3, stride 2, pad 1, relu =================
__global__ void enc1_kernel(const float* __restrict__ x,
                            const float* __restrict__ w,
                            const float* __restrict__ bias) {
    __shared__ float ws[3456]; // [c][ky][kx][128]
    int oy = blockIdx.x, b = blockIdx.y;
    int tid = threadIdx.x;
    for (int e = tid; e < 3456; e += 256) {
        int oc = e & 127; int t = e >> 7;
        int c = t / 9; int r = t - c * 9; int ky = r / 3, kx = r - ky * 3;
        ws[e] = w[((oc * 3 + c) * 3 + ky) * 3 + kx];
    }
    __syncthreads();
    int ox = tid & 63, ocg = tid >> 6;
    float acc[32];
#pragma unroll
    for (int i = 0; i < 32; i++) acc[i] = __ldg(bias + ocg * 32 + i);
    const float* xb = x + b * 3 * 128 * 128;
#pragma unroll
    for (int c = 0; c < 3; c++) {
#pragma unroll
        for (int ky = 0; ky < 3; ky++) {
            int iy = 2 * oy + ky - 1;
#pragma unroll
            for (int kx = 0; kx < 3; kx++) {
                int ix = 2 * ox + kx - 1;
                float xv = 0.f;
                if ((unsigned)iy < 128u && (unsigned)ix < 128u)
                    xv = __ldg(xb + (c * 128 + iy) * 128 + ix);
                const float* wp = &ws[((c * 3 + ky) * 3 + kx) * 128 + ocg * 32];
#pragma unroll
                for (int q = 0; q < 8; q++) {
                    float4 wv = *(const float4*)(wp + q * 4);
                    acc[q * 4 + 0] += wv.x * xv;
                    acc[q * 4 + 1] += wv.y * xv;
                    acc[q * 4 + 2] += wv.z * xv;
                    acc[q * 4 + 3] += wv.w * xv;
                }
            }
        }
    }
    float* op = g_h1 + ((b * 128 + ocg * 32) * 64 + oy) * 64 + ox;
#pragma unroll
    for (int i = 0; i < 32; i++) op[i * 64 * 64] = fmaxf(acc[i], 0.f);
}

// ================= encoder conv2 main: split-K halves, raw partials =================
// grid (32 b, 4 y=[ocg|half], 8 gy), 256 thr; block tile = 64 oc x (4 rows x 32 cols) over 64 ic.
__global__ void __launch_bounds__(256, 4) enc2_main_kernel() {
    __shared__ float sm[9504];
    float* s_in = sm;         // 8 ic * (9 rows * 68): per row E[0..31] @ +0, O[0..32] @ +32
    float* s_w  = sm + 4896;  // 8 ic * 9 tap * 64 oc
    int b = blockIdx.x;
    int ocg = blockIdx.y >> 1, half = blockIdx.y & 1;
    int gy = blockIdx.z;
    int tid = threadIdx.x;
    int lane = tid & 31;
    int ocq  = tid >> 5;
    int r    = lane >> 3;     // out row 0..3
    int cg   = lane & 7;      // col group (4 cols)

    int icS = tid >> 5;
    int off0 = (lane & 1) ? ((lane - 1) >> 1) : (32 + (lane >> 1));           // cc = lane
    int off1 = (lane & 1) ? ((lane + 31) >> 1) : (32 + ((lane + 32) >> 1));   // cc = lane+32

    float acc[8][4];
#pragma unroll
    for (int i = 0; i < 8; i++)
#pragma unroll
        for (int p = 0; p < 4; p++) acc[i][p] = 0.f;

    for (int chl = 0; chl < 8; chl++) {
        int ch = half * 8 + chl;
        __syncthreads();
        // ---- stage inputs ----
        {
            const float* src = g_h1 + (((size_t)b * 128 + ch * 8 + icS) * 64) * 64;
            float* dst = s_in + icS * 612;
            int iy0 = gy * 8 - 1;
#pragma unroll
            for (int rr = 0; rr < 9; rr++) {
                int iy = iy0 + rr;
                bool rowok = (unsigned)iy < 64u;
                const float* srow = src + iy * 64;
                {
                    int ix = lane - 1;
                    float v = (rowok && (unsigned)ix < 64u) ? srow[ix] : 0.f;
                    dst[rr * 68 + off0] = v;
                }
                {
                    int ix = lane + 31;
                    float v = (rowok && ix < 64) ? srow[ix] : 0.f;
                    dst[rr * 68 + off1] = v;
                }
            }
            if (lane < 9) {
                int iy = iy0 + lane;
                float v = ((unsigned)iy < 64u) ? src[iy * 64 + 63] : 0.f;
                dst[lane * 68 + 64] = v;
            }
        }
        // ---- stage weights ----
        {
            const float* wsrc = g_w2t + (size_t)ch * 72 * 128 + ocg * 64;
#pragma unroll
            for (int k = 0; k < 18; k++) {
                int e = k * 256 + tid;
                int rowi = e >> 6, ocl = e & 63;
                s_w[e] = wsrc[rowi * 128 + ocl];
            }
        }
        __syncthreads();
#pragma unroll
        for (int ic = 0; ic < 8; ic++) {
            const float* sib = s_in + ic * 612;
            const float* swb = s_w + ic * 576 + ocq * 8;
#pragma unroll
            for (int ky = 0; ky < 3; ky++) {
                const float* rp = sib + (2 * r + ky) * 68;
                float4 E4 = *(const float4*)(rp + 4 * cg);
                float4 O4 = *(const float4*)(rp + 32 + 4 * cg);
                float  O1 = rp[36 + 4 * cg];
                float in0[4] = {O4.x, O4.y, O4.z, O4.w};   // kx=0
                float in1[4] = {E4.x, E4.y, E4.z, E4.w};   // kx=1
                float in2[4] = {O4.y, O4.z, O4.w, O1};     // kx=2
#pragma unroll
                for (int kx = 0; kx < 3; kx++) {
                    const float* wp = swb + (ky * 3 + kx) * 64;
                    float4 wA = *(const float4*)wp;
                    float4 wB = *(const float4*)(wp + 4);
                    float wr[8] = {wA.x, wA.y, wA.z, wA.w, wB.x, wB.y, wB.z, wB.w};
                    const float* in = (kx == 0) ? in0 : (kx == 1) ? in1 : in2;
#pragma unroll
                    for (int i = 0; i < 8; i++) {
#pragma unroll
                        for (int p = 0; p < 4; p++) acc[i][p] += wr[i] * in[p];
                    }
                }
            }
        }
    }
    // write raw partials: [b][ocg][half][gy][oc64][row4][col32]
    float* op = g_p2 + ((((size_t)b * 2 + ocg) * 2 + half) * 8 + gy) * 8192;
#pragma unroll
    for (int i = 0; i < 8; i++) {
        float4 v = make_float4(acc[i][0], acc[i][1], acc[i][2], acc[i][3]);
        *(float4*)(op + (ocq * 8 + i) * 128 + r * 32 + 4 * cg) = v;
    }
}

// ================= enc2 reduce: sum halves + bias + relu + 4x4 pool =================
// grid (32 b, 2 ocg, 8 gy), 256 thr; 512 outputs (64 oc x 8 gx) per block.
__global__ void enc2_reduce_kernel(const float* __restrict__ bias) {
    int b = blockIdx.x, ocg = blockIdx.y, gy = blockIdx.z;
    int tid = threadIdx.x;
    const float* p0 = g_p2 + ((((size_t)b * 2 + ocg) * 2 + 0) * 8 + gy) * 8192;
    const float* p1 = g_p2 + ((((size_t)b * 2 + ocg) * 2 + 1) * 8 + gy) * 8192;
#pragma unroll
    for (int t = 0; t < 2; t++) {
        int o = t * 256 + tid;       // 0..511
        int oc = o >> 3, gx = o & 7;
        float bv = __ldg(bias + ocg * 64 + oc);
        float s = 0.f;
#pragma unroll
        for (int r = 0; r < 4; r++) {
            float4 a = *(const float4*)(p0 + oc * 128 + r * 32 + 4 * gx);
            float4 c = *(const float4*)(p1 + oc * 128 + r * 32 + 4 * gx);
            s += fmaxf(a.x + c.x + bv, 0.f) + fmaxf(a.y + c.y + bv, 0.f)
               + fmaxf(a.z + c.z + bv, 0.f) + fmaxf(a.w + c.w + bv, 0.f);
        }
        g_hp[((b * 128 + ocg * 64 + oc) * 8 + gy) * 8 + gx] = s * (1.f / 16.f);
    }
}

// ================= proj 1x1: 128 -> 64, writes z_e straight into d_out slot =================
__global__ void proj_kernel(const float* __restrict__ w,
                            const float* __restrict__ bias,
                            float* __restrict__ zout) {
    __shared__ float s_hp[8192]; // [hc][pos]
    int b = blockIdx.x, tid = threadIdx.x;
    for (int e = tid; e < 8192; e += 256) s_hp[e] = g_hp[b * 8192 + e];
    __syncthreads();
    int pos = tid & 63, dg = tid >> 6;
    for (int dl = 0; dl < 16; dl++) {
        int d = dg * 16 + dl;
        float acc = __ldg(bias + d);
        const float* wr = w + d * 128;
#pragma unroll 8
        for (int hc = 0; hc < 128; hc++) acc += __ldg(wr + hc) * s_hp[hc * 64 + pos];
        zout[(b * 64 + d) * 64 + pos] = acc;
    }
}

// ================= vector quantizer: smem-tiled, coalesced, per-image loss partial =================
__global__ void __launch_bounds__(512) vq_kernel(const float* __restrict__ z,
                                                 const float* __restrict__ cb,
                                                 float* __restrict__ idx_out) {
    __shared__ float s_z[64 * 68];
    __shared__ float s_c[64 * 68];
    __shared__ float s_rv[512];
    __shared__ int   s_ri[512];
    int b = blockIdx.x, tid = threadIdx.x;
    int pos = tid & 63, kq = tid >> 6;
    for (int e = tid; e < 4096; e += 512) {
        int d = e >> 6, p = e & 63;
        s_z[p * 68 + d] = z[(b * 64 + d) * 64 + p];
    }
    float bestv = 3.4e38f; int besti = 0;
    for (int t = 0; t < 8; t++) {
        __syncthreads();
        for (int e = tid; e < 4096; e += 512) {
            int k = e >> 6, d = e & 63;
            s_c[k * 68 + d] = __ldg(cb + (t * 64 + k) * 64 + d);
        }
        __syncthreads();
        float acc[8];
#pragma unroll
        for (int j = 0; j < 8; j++) acc[j] = 0.f;
        const float* zp = s_z + pos * 68;
        for (int d = 0; d < 64; d += 4) {
            float4 z4 = *(const float4*)(zp + d);
#pragma unroll
            for (int j = 0; j < 8; j++) {
                float4 c4 = *(const float4*)(s_c + (kq * 8 + j) * 68 + d);
                float d0 = c4.x - z4.x; acc[j] += d0 * d0;
                float d1 = c4.y - z4.y; acc[j] += d1 * d1;
                float d2 = c4.z - z4.z; acc[j] += d2 * d2;
                float d3 = c4.w - z4.w; acc[j] += d3 * d3;
            }
        }
#pragma unroll
        for (int j = 0; j < 8; j++) {
            int k = t * 64 + kq * 8 + j;
            if (acc[j] < bestv) { bestv = acc[j]; besti = k; }
        }
    }
    s_rv[tid] = bestv; s_ri[tid] = besti;
    __syncthreads();
    if (tid < 64) {
        float bv = s_rv[tid]; int bi = s_ri[tid];
#pragma unroll
        for (int q = 1; q < 8; q++) {
            float v = s_rv[q * 64 + tid]; int i2 = s_ri[q * 64 + tid];
            if (v < bv || (v == bv && i2 < bi)) { bv = v; bi = i2; }
        }
        int n = b * 64 + tid;
        g_idx[n] = bi;
        idx_out[n] = (float)bi;
        s_rv[tid] = bv;
    }
    __syncthreads();
    if (tid == 0) {
        float s = 0.f;
        for (int i = 0; i < 64; i++) s += s_rv[i];
        g_loss_part[b] = s;
    }
}

__global__ void finalize_loss_kernel(float* __restrict__ out) {
    float s = 0.f;
    for (int i = 0; i < 32; i++) s += g_loss_part[i];
    out[0] = s * (1.25f / 131072.f);
}

// ================= dproj 1x1: 64 -> 128 on quantized codes, relu (pre-upsample) =================
__global__ void dproj_kernel(const float* __restrict__ cb,
                             const float* __restrict__ w,
                             const float* __restrict__ bias) {
    __shared__ float s_zq[4096]; // [d][pos]
    __shared__ int   s_i[64];
    int b = blockIdx.x, tid = threadIdx.x;
    if (tid < 64) s_i[tid] = g_idx[b * 64 + tid];
    __syncthreads();
    for (int e = tid; e < 4096; e += 256) {
        int d = e >> 6, pos = e & 63;
        s_zq[e] = __ldg(cb + s_i[pos] * 64 + d);
    }
    __syncthreads();
    int pos = tid & 63, hg = tid >> 6;
    for (int h = 0; h < 32; h++) {
        int hc = hg * 32 + h;
        float acc = __ldg(bias + hc);
        const float* wr = w + hc * 64;
#pragma unroll 8
        for (int d = 0; d < 64; d++) acc += __ldg(wr + d) * s_zq[d * 64 + pos];
        g_y[b * 8192 + hc * 64 + pos] = fmaxf(acc, 0.f);
    }
}

// ================= dconv1 weight-subset precompute: 25 matrices [m][ic][oc] =================
__global__ void w25_kernel(const float* __restrict__ w) {
    int g = blockIdx.x * 256 + threadIdx.x;
    if (g >= 25 * 16384) return;
    int m = g >> 14; int r = g & 16383; int ic = r & 127; int oc = r >> 7;
    int sy = m / 5, sx = m - sy * 5;
    const int mask[5] = {1, 4, 3, 6, 7};
    float s = 0.f;
    for (int j = 0; j < 3; j++) if ((mask[sy] >> j) & 1)
        for (int i = 0; i < 3; i++) if ((mask[sx] >> i) & 1)
            s += __ldg(w + ((oc * 128 + ic) * 3 + j) * 3 + i);
    g_w25[(m * 128 + ic) * 128 + oc] = s;
}

// ================= dconv1: job-table balanced (18 jobs/image, 64 oc each, heavy first) =================
__device__ const signed char c_jobs[18][2] = {
    {0,0},{0,1},{2,0},{2,1},{6,0},{6,1},{8,0},{8,1},   // corners (4 passes)
    {1,0},{1,1},{3,0},{3,1},{5,0},{5,1},{7,0},{7,1},   // edges   (2 passes)
    {4,0},{4,1}                                         // mid     (1 pass)
};
__global__ void dconv1_blocks_kernel(const float* __restrict__ bias) {
    __shared__ float s_y[8192]; // [ic][pos]
    int b = blockIdx.x;
    int vt = c_jobs[blockIdx.y][0], ochalf = c_jobs[blockIdx.y][1];
    int tid = threadIdx.x;
    for (int e = tid; e < 8192; e += 256) s_y[e] = g_y[b * 8192 + e];
    __syncthreads();

    int lane = tid & 31;
    int ocb = ochalf * 64 + (tid >> 5) * 8;
    int ty = vt / 3, tx = vt - ty * 3;

    int nyp, ys[2], ydy[2];
    if (ty == 0)      { nyp = 2; ys[0] = 0; ydy[0] = -1; ys[1] = 3; ydy[1] = 0; }
    else if (ty == 1) { nyp = 1; ys[0] = 4; ydy[0] = 0;  ys[1] = 0; ydy[1] = 0; }
    else              { nyp = 2; ys[0] = 2; ydy[0] = 0;  ys[1] = 1; ydy[1] = 1; }
    int nxp, xs[2], xdx[2];
    if (tx == 0)      { nxp = 2; xs[0] = 0; xdx[0] = -1; xs[1] = 3; xdx[1] = 0; }
    else if (tx == 1) { nxp = 1; xs[0] = 4; xdx[0] = 0;  xs[1] = 0; xdx[1] = 0; }
    else              { nxp = 2; xs[0] = 2; xdx[0] = 0;  xs[1] = 1; xdx[1] = 1; }

    float acc0[8], acc1[8];
#pragma unroll
    for (int i = 0; i < 8; i++) { acc0[i] = __ldg(bias + ocb + i); acc1[i] = acc0[i]; }

    int pos0 = lane, pos1 = lane + 32;
    int gy0 = pos0 >> 3, gx0 = pos0 & 7;
    int gy1 = pos1 >> 3, gx1 = pos1 & 7;

    for (int a = 0; a < nyp; a++) {
        for (int c = 0; c < nxp; c++) {
            int m = ys[a] * 5 + xs[c];
            int dy = ydy[a], dx = xdx[c];
            int ny0 = gy0 + dy, nx0 = gx0 + dx;
            int ny1 = gy1 + dy, nx1 = gx1 + dx;
            bool v0 = ((unsigned)ny0 < 8u) && ((unsigned)nx0 < 8u);
            bool v1 = ((unsigned)ny1 < 8u) && ((unsigned)nx1 < 8u);
            int np0 = ny0 * 8 + nx0, np1 = ny1 * 8 + nx1;
            const float* wbase = g_w25 + (m * 128) * 128 + ocb;
#pragma unroll 4
            for (int ic = 0; ic < 128; ic++) {
                float yv0 = v0 ? s_y[ic * 64 + np0] : 0.f;
                float yv1 = v1 ? s_y[ic * 64 + np1] : 0.f;
                const float* wp = wbase + ic * 128;
                float4 wv0 = __ldg((const float4*)wp);
                float4 wv1 = __ldg((const float4*)wp + 1);
                acc0[0] += wv0.x * yv0; acc1[0] += wv0.x * yv1;
                acc0[1] += wv0.y * yv0; acc1[1] += wv0.y * yv1;
                acc0[2] += wv0.z * yv0; acc1[2] += wv0.z * yv1;
                acc0[3] += wv0.w * yv0; acc1[3] += wv0.w * yv1;
                acc0[4] += wv1.x * yv0; acc1[4] += wv1.x * yv1;
                acc0[5] += wv1.y * yv0; acc1[5] += wv1.y * yv1;
                acc0[6] += wv1.z * yv0; acc1[6] += wv1.z * yv1;
                acc0[7] += wv1.w * yv0; acc1[7] += wv1.w * yv1;
            }
        }
    }
    float* op = g_r9 + ((size_t)(b * 9 + vt) * 128 + ocb) * 64;
#pragma unroll
    for (int i = 0; i < 8; i++) {
        op[i * 64 + pos0] = fmaxf(acc0[i], 0.f);
        op[i * 64 + pos1] = fmaxf(acc1[i], 0.f);
    }
}

// ================= dconv2 1x1 (128->3) on 9 block values + scatter to full image =================
__global__ void dconv2_scatter_kernel(const float* __restrict__ w,
                                      const float* __restrict__ bias,
                                      float* __restrict__ xhat) {
    __shared__ float s_r[1152]; // [vt][oc]
    __shared__ float s_v[27];   // [vt][co]
    int pos = blockIdx.x, b = blockIdx.y;
    int tid = threadIdx.x;
    for (int e = tid; e < 1152; e += 128) {
        int vt = e >> 7, oc = e & 127;
        s_r[e] = g_r9[((size_t)(b * 9 + vt) * 128 + oc) * 64 + pos];
    }
    __syncthreads();
    if (tid < 27) {
        int vt = tid / 3, co = tid - vt * 3;
        float acc = __ldg(bias + co);
        const float* wr = w + co * 128;
        const float* rr = s_r + vt * 128;
#pragma unroll 8
        for (int oc = 0; oc < 128; oc++) acc += __ldg(wr + oc) * rr[oc];
        s_v[tid] = acc;
    }
    __syncthreads();
    int gy = pos >> 3, gx = pos & 7;
    for (int pp = tid; pp < 256; pp += 128) {
        int ly = pp >> 4, lx = pp & 15;
        int ty2 = (ly == 0) ? 0 : ((ly == 15) ? 2 : 1);
        int tx2 = (lx == 0) ? 0 : ((lx == 15) ? 2 : 1);
        int vtp = ty2 * 3 + tx2;
        int py = gy * 16 + ly, px = gx * 16 + lx;
#pragma unroll
        for (int co = 0; co < 3; co++)
            xhat[((b * 3 + co) * 128 + py) * 128 + px] = s_v[vtp * 3 + co];
    }
}

// ================= launch =================
extern "C" void kernel_launch(void* const* d_in, const int* in_sizes, int n_in,
                              void* d_out, int out_size) {
    const float* x   = (const float*)d_in[0];
    const float* ew1 = (const float*)d_in[1];
    const float* eb1 = (const float*)d_in[2];
    const float* ew2 = (const float*)d_in[3];
    const float* eb2 = (const float*)d_in[4];
    const float* pw  = (const float*)d_in[5];
    const float* pb  = (const float*)d_in[6];
    const float* cb  = (const float*)d_in[7];
    const float* dpw = (const float*)d_in[8];
    const float* dpb = (const float*)d_in[9];
    const float* dw1 = (const float*)d_in[10];
    const float* db1 = (const float*)d_in[11];
    const float* dw2 = (const float*)d_in[12];
    const float* db2 = (const float*)d_in[13];

    float* out   = (float*)d_out;
    float* xhat  = out;               // 32*3*128*128 = 1572864
    float* idxo  = out + 1572864;     // 32*8*8       = 2048
    float* losso = out + 1574912;     // 1
    float* zeo   = out + 1574913;     // 32*64*8*8    = 131072

    // order keeps enc2 main at the profiled launch ordinal (#4)
    w2t_kernel<<<576, 256>>>(ew2);
    w25_kernel<<<1600, 256>>>(dw1);
    enc1_kernel<<<dim3(64, 32), 256>>>(x, ew1, eb1);
    enc2_main_kernel<<<dim3(32, 4, 8), 256>>>();
    enc2_reduce_kernel<<<dim3(32, 2, 8), 256>>>(eb2);
    proj_kernel<<<32, 256>>>(pw, pb, zeo);
    vq_kernel<<<32, 512>>>(zeo, cb, idxo);
    finalize_loss_kernel<<<1, 1>>>(losso);
    dproj_kernel<<<32, 256>>>(cb, dpw, dpb);
    dconv1_blocks_kernel<<<dim3(32, 18), 256>>>(db1);
    dconv2_scatter_kernel<<<dim3(64, 32), 128>>>(dw2, db2, xhat);
}

// round 14
// speedup vs baseline: 3.7189x; 1.4179x over previous
#include <cuda_runtime.h>
#include <cuda_bf16.h>
#include <cstdint>

// ---------------- problem constants ----------------
// x:(32,3,128,128)  enc1->(32,128,64,64)  enc2->(32,128,32,32) pool->(32,128,8,8)
// proj-> z_e (32,64,8,8)  VQ K=512,D=64  dproj->(32,128,8,8) up x16 -> dconv1 -> dconv2 -> (32,3,128,128)

// ---------------- device scratch (no allocations allowed) ----------------
__device__ float g_h1[32 * 128 * 64 * 64];        // enc1 output fp32 (64 MB)
__device__ float g_p2[32 * 2 * 2 * 8 * 64 * 128]; // enc2 split-K partials (67 MB)
__device__ float g_hp[32 * 128 * 8 * 8];          // pooled encoder features
__device__ uint32_t g_yp[32 * 128 * 8 * 8];       // dproj output relu'd, packed bf16 h|l
__device__ float g_r9[32 * 9 * 128 * 64];         // dconv1: 9 values per 16x16 block
__device__ float g_w25[25 * 128 * 128];           // dconv1 weight subsets [m][ic][oc]
__device__ float g_w2t[128 * 9 * 128];            // enc2 weights transposed [ic][tap][oc]
__device__ uint32_t g_wd1h[25 * 4 * 128 * 16];    // dconv1 weights bf16-h [m][q][oc][kpair]
__device__ uint32_t g_wd1l[25 * 4 * 128 * 16];    // dconv1 weights bf16-l
__device__ int   g_idx[2048];
__device__ float g_loss_part[32];
__device__ float g_vqv[32 * 4 * 64];
__device__ int   g_vqi[32 * 4 * 64];

// ================= helpers =================
__device__ __forceinline__ uint32_t smem_u32(const void* p) {
    uint32_t a;
    asm("{ .reg .u64 t; cvta.to.shared.u64 t, %1; cvt.u32.u64 %0, t; }" : "=r"(a) : "l"(p));
    return a;
}
__device__ __forceinline__ void ldm_x4(uint32_t* r, uint32_t a) {
    asm volatile("ldmatrix.sync.aligned.m8n8.x4.shared.b16 {%0,%1,%2,%3}, [%4];"
                 : "=r"(r[0]), "=r"(r[1]), "=r"(r[2]), "=r"(r[3]) : "r"(a));
}
__device__ __forceinline__ void ldm_x4_t(uint32_t* r, uint32_t a) {
    asm volatile("ldmatrix.sync.aligned.m8n8.x4.trans.shared.b16 {%0,%1,%2,%3}, [%4];"
                 : "=r"(r[0]), "=r"(r[1]), "=r"(r[2]), "=r"(r[3]) : "r"(a));
}
__device__ __forceinline__ void mma16816(float* d, const uint32_t* a, uint32_t b0, uint32_t b1) {
    asm volatile("mma.sync.aligned.m16n8k16.row.col.f32.bf16.bf16.f32 "
                 "{%0,%1,%2,%3}, {%4,%5,%6,%7}, {%8,%9}, {%0,%1,%2,%3};"
                 : "+f"(d[0]), "+f"(d[1]), "+f"(d[2]), "+f"(d[3])
                 : "r"(a[0]), "r"(a[1]), "r"(a[2]), "r"(a[3]), "r"(b0), "r"(b1));
}
// 2-way bf16 split packed: lo16 = h, hi16 = l, v = h + l (residual ~2^-18 v)
__device__ __forceinline__ uint32_t pack_hl(float v) {
    __nv_bfloat16 h = __float2bfloat16(v);
    __nv_bfloat16 l = __float2bfloat16(v - __bfloat162float(h));
    return (uint32_t)__bfloat16_as_ushort(h) | ((uint32_t)__bfloat16_as_ushort(l) << 16);
}

// ================= enc2 weight transpose: w[oc][ic][ky][kx] -> g_w2t[ic][tap][oc] =================
__global__ void w2t_kernel(const float* __restrict__ w) {
    int e = blockIdx.x * 256 + threadIdx.x;   // 147456 elements
    if (e >= 147456) return;
    int oc = e & 127; int t = e >> 7;         // t = ic*9 + tap
    int tap = t % 9; int icf = t / 9;
    g_w2t[e] = __ldg(w + (oc * 128 + icf) * 9 + tap);
}

// ================= encoder conv1: 3->128, 3x3, stride 2, pad 1, relu =================
__global__ void enc1_kernel(const float* __restrict__ x,
                            const float* __restrict__ w,
                            const float* __restrict__ bias) {
    __shared__ float ws[3456]; // [c][ky][kx][128]
    int oy = blockIdx.x, b = blockIdx.y;
    int tid = threadIdx.x;
    for (int e = tid; e < 3456; e += 256) {
        int oc = e & 127; int t = e >> 7;
        int c = t / 9; int r = t - c * 9; int ky = r / 3, kx = r - ky * 3;
        ws[e] = w[((oc * 3 + c) * 3 + ky) * 3 + kx];
    }
    __syncthreads();
    int ox = tid & 63, ocg = tid >> 6;
    float acc[32];
#pragma unroll
    for (int i = 0; i < 32; i++) acc[i] = __ldg(bias + ocg * 32 + i);
    const float* xb = x + b * 3 * 128 * 128;
#pragma unroll
    for (int c = 0; c < 3; c++) {
#pragma unroll
        for (int ky = 0; ky < 3; ky++) {
            int iy = 2 * oy + ky - 1;
#pragma unroll
            for (int kx = 0; kx < 3; kx++) {
                int ix = 2 * ox + kx - 1;
                float xv = 0.f;
                if ((unsigned)iy < 128u && (unsigned)ix < 128u)
                    xv = __ldg(xb + (c * 128 + iy) * 128 + ix);
                const float* wp = &ws[((c * 3 + ky) * 3 + kx) * 128 + ocg * 32];
#pragma unroll
                for (int q = 0; q < 8; q++) {
                    float4 wv = *(const float4*)(wp + q * 4);
                    acc[q * 4 + 0] += wv.x * xv;
                    acc[q * 4 + 1] += wv.y * xv;
                    acc[q * 4 + 2] += wv.z * xv;
                    acc[q * 4 + 3] += wv.w * xv;
                }
            }
        }
    }
    float* op = g_h1 + ((b * 128 + ocg * 32) * 64 + oy) * 64 + ox;
#pragma unroll
    for (int i = 0; i < 32; i++) op[i * 64 * 64] = fmaxf(acc[i], 0.f);
}

// ================= encoder conv2 main: split-K halves, raw partials (fp32) =================
// grid (32 b, 4 y=[ocg|half], 8 gy), 256 thr; block tile = 64 oc x (4 rows x 32 cols) over 64 ic.
__global__ void __launch_bounds__(256, 4) enc2_main_kernel() {
    __shared__ float sm[9504];
    float* s_in = sm;         // 8 ic * (9 rows * 68): per row E[0..31] @ +0, O[0..32] @ +32
    float* s_w  = sm + 4896;  // 8 ic * 9 tap * 64 oc
    int b = blockIdx.x;
    int ocg = blockIdx.y >> 1, half = blockIdx.y & 1;
    int gy = blockIdx.z;
    int tid = threadIdx.x;
    int lane = tid & 31;
    int ocq  = tid >> 5;
    int r    = lane >> 3;     // out row 0..3
    int cg   = lane & 7;      // col group (4 cols)

    int icS = tid >> 5;
    int off0 = (lane & 1) ? ((lane - 1) >> 1) : (32 + (lane >> 1));           // cc = lane
    int off1 = (lane & 1) ? ((lane + 31) >> 1) : (32 + ((lane + 32) >> 1));   // cc = lane+32

    float acc[8][4];
#pragma unroll
    for (int i = 0; i < 8; i++)
#pragma unroll
        for (int p = 0; p < 4; p++) acc[i][p] = 0.f;

    for (int chl = 0; chl < 8; chl++) {
        int ch = half * 8 + chl;
        __syncthreads();
        {
            const float* src = g_h1 + (((size_t)b * 128 + ch * 8 + icS) * 64) * 64;
            float* dst = s_in + icS * 612;
            int iy0 = gy * 8 - 1;
#pragma unroll
            for (int rr = 0; rr < 9; rr++) {
                int iy = iy0 + rr;
                bool rowok = (unsigned)iy < 64u;
                const float* srow = src + iy * 64;
                {
                    int ix = lane - 1;
                    float v = (rowok && (unsigned)ix < 64u) ? srow[ix] : 0.f;
                    dst[rr * 68 + off0] = v;
                }
                {
                    int ix = lane + 31;
                    float v = (rowok && ix < 64) ? srow[ix] : 0.f;
                    dst[rr * 68 + off1] = v;
                }
            }
            if (lane < 9) {
                int iy = iy0 + lane;
                float v = ((unsigned)iy < 64u) ? src[iy * 64 + 63] : 0.f;
                dst[lane * 68 + 64] = v;
            }
        }
        {
            const float* wsrc = g_w2t + (size_t)ch * 72 * 128 + ocg * 64;
#pragma unroll
            for (int k = 0; k < 18; k++) {
                int e = k * 256 + tid;
                int rowi = e >> 6, ocl = e & 63;
                s_w[e] = wsrc[rowi * 128 + ocl];
            }
        }
        __syncthreads();
#pragma unroll
        for (int ic = 0; ic < 8; ic++) {
            const float* sib = s_in + ic * 612;
            const float* swb = s_w + ic * 576 + ocq * 8;
#pragma unroll
            for (int ky = 0; ky < 3; ky++) {
                const float* rp = sib + (2 * r + ky) * 68;
                float4 E4 = *(const float4*)(rp + 4 * cg);
                float4 O4 = *(const float4*)(rp + 32 + 4 * cg);
                float  O1 = rp[36 + 4 * cg];
                float in0[4] = {O4.x, O4.y, O4.z, O4.w};   // kx=0
                float in1[4] = {E4.x, E4.y, E4.z, E4.w};   // kx=1
                float in2[4] = {O4.y, O4.z, O4.w, O1};     // kx=2
#pragma unroll
                for (int kx = 0; kx < 3; kx++) {
                    const float* wp = swb + (ky * 3 + kx) * 64;
                    float4 wA = *(const float4*)wp;
                    float4 wB = *(const float4*)(wp + 4);
                    float wr[8] = {wA.x, wA.y, wA.z, wA.w, wB.x, wB.y, wB.z, wB.w};
                    const float* in = (kx == 0) ? in0 : (kx == 1) ? in1 : in2;
#pragma unroll
                    for (int i = 0; i < 8; i++) {
#pragma unroll
                        for (int p = 0; p < 4; p++) acc[i][p] += wr[i] * in[p];
                    }
                }
            }
        }
    }
    float* op = g_p2 + ((((size_t)b * 2 + ocg) * 2 + half) * 8 + gy) * 8192;
#pragma unroll
    for (int i = 0; i < 8; i++) {
        float4 v = make_float4(acc[i][0], acc[i][1], acc[i][2], acc[i][3]);
        *(float4*)(op + (ocq * 8 + i) * 128 + r * 32 + 4 * cg) = v;
    }
}

// ================= enc2 reduce: sum halves + bias + relu + 4x4 pool =================
__global__ void enc2_reduce_kernel(const float* __restrict__ bias) {
    int b = blockIdx.x, ocg = blockIdx.y, gy = blockIdx.z;
    int tid = threadIdx.x;
    const float* p0 = g_p2 + ((((size_t)b * 2 + ocg) * 2 + 0) * 8 + gy) * 8192;
    const float* p1 = g_p2 + ((((size_t)b * 2 + ocg) * 2 + 1) * 8 + gy) * 8192;
#pragma unroll
    for (int t = 0; t < 2; t++) {
        int o = t * 256 + tid;       // 0..511
        int oc = o >> 3, gx = o & 7;
        float bv = __ldg(bias + ocg * 64 + oc);
        float s = 0.f;
#pragma unroll
        for (int r = 0; r < 4; r++) {
            float4 a = *(const float4*)(p0 + oc * 128 + r * 32 + 4 * gx);
            float4 c = *(const float4*)(p1 + oc * 128 + r * 32 + 4 * gx);
            s += fmaxf(a.x + c.x + bv, 0.f) + fmaxf(a.y + c.y + bv, 0.f)
               + fmaxf(a.z + c.z + bv, 0.f) + fmaxf(a.w + c.w + bv, 0.f);
        }
        g_hp[((b * 128 + ocg * 64 + oc) * 8 + gy) * 8 + gx] = s * (1.f / 16.f);
    }
}

// ================= proj 1x1: 128 -> 64 (fp32 exact, feeds argmin) =================
__global__ void proj_kernel(const float* __restrict__ w,
                            const float* __restrict__ bias,
                            float* __restrict__ zout) {
    __shared__ float s_hp[8192]; // [hc][pos]
    int b = blockIdx.x, tid = threadIdx.x;
    for (int e = tid; e < 8192; e += 256) s_hp[e] = g_hp[b * 8192 + e];
    __syncthreads();
    int pos = tid & 63, dg = tid >> 6;
    for (int dl = 0; dl < 16; dl++) {
        int d = dg * 16 + dl;
        float acc = __ldg(bias + d);
        const float* wr = w + d * 128;
#pragma unroll 8
        for (int hc = 0; hc < 128; hc++) acc += __ldg(wr + hc) * s_hp[hc * 64 + pos];
        zout[(b * 64 + d) * 64 + pos] = acc;
    }
}

// ================= vector quantizer: 4-wide partials + final reduce =================
__global__ void __launch_bounds__(512) vq_part_kernel(const float* __restrict__ z,
                                                      const float* __restrict__ cb) {
    __shared__ float s_z[64 * 68];
    __shared__ float s_c[64 * 68];
    __shared__ float s_rv[512];
    __shared__ int   s_ri[512];
    int b = blockIdx.x, part = blockIdx.y, tid = threadIdx.x;
    int pos = tid & 63, kq = tid >> 6;
    for (int e = tid; e < 4096; e += 512) {
        int d = e >> 6, p = e & 63;
        s_z[p * 68 + d] = z[(b * 64 + d) * 64 + p];
    }
    float bestv = 3.4e38f; int besti = 0;
    for (int t = 0; t < 2; t++) {
        __syncthreads();
        for (int e = tid; e < 4096; e += 512) {
            int k = e >> 6, d = e & 63;
            s_c[k * 68 + d] = __ldg(cb + ((part * 2 + t) * 64 + k) * 64 + d);
        }
        __syncthreads();
        float accq[8];
#pragma unroll
        for (int j = 0; j < 8; j++) accq[j] = 0.f;
        const float* zp = s_z + pos * 68;
        for (int d = 0; d < 64; d += 4) {
            float4 z4 = *(const float4*)(zp + d);
#pragma unroll
            for (int j = 0; j < 8; j++) {
                float4 c4 = *(const float4*)(s_c + (kq * 8 + j) * 68 + d);
                float d0 = c4.x - z4.x; accq[j] += d0 * d0;
                float d1 = c4.y - z4.y; accq[j] += d1 * d1;
                float d2 = c4.z - z4.z; accq[j] += d2 * d2;
                float d3 = c4.w - z4.w; accq[j] += d3 * d3;
            }
        }
#pragma unroll
        for (int j = 0; j < 8; j++) {
            int k = (part * 2 + t) * 64 + kq * 8 + j;
            if (accq[j] < bestv) { bestv = accq[j]; besti = k; }
        }
    }
    s_rv[tid] = bestv; s_ri[tid] = besti;
    __syncthreads();
    if (tid < 64) {
        float bv = s_rv[tid]; int bi = s_ri[tid];
#pragma unroll
        for (int q = 1; q < 8; q++) {
            float v = s_rv[q * 64 + tid]; int i2 = s_ri[q * 64 + tid];
            if (v < bv || (v == bv && i2 < bi)) { bv = v; bi = i2; }
        }
        g_vqv[(b * 4 + part) * 64 + tid] = bv;
        g_vqi[(b * 4 + part) * 64 + tid] = bi;
    }
}

__global__ void vq_final_kernel(float* __restrict__ idx_out) {
    __shared__ float sv[64];
    int b = blockIdx.x, tid = threadIdx.x;  // tid = pos
    float bv = g_vqv[(b * 4 + 0) * 64 + tid];
    int   bi = g_vqi[(b * 4 + 0) * 64 + tid];
#pragma unroll
    for (int part = 1; part < 4; part++) {
        float v = g_vqv[(b * 4 + part) * 64 + tid];
        int  i2 = g_vqi[(b * 4 + part) * 64 + tid];
        if (v < bv || (v == bv && i2 < bi)) { bv = v; bi = i2; }
    }
    int n = b * 64 + tid;
    g_idx[n] = bi;
    idx_out[n] = (float)bi;
    sv[tid] = bv;
    __syncthreads();
    if (tid == 0) {
        float s = 0.f;
        for (int i = 0; i < 64; i++) s += sv[i];
        g_loss_part[b] = s;
    }
}

__global__ void finalize_loss_kernel(float* __restrict__ out) {
    float s = 0.f;
    for (int i = 0; i < 32; i++) s += g_loss_part[i];
    out[0] = s * (1.25f / 131072.f);
}

// ================= dproj 1x1: 64 -> 128, relu -> packed bf16 h|l =================
__global__ void dproj_kernel(const float* __restrict__ cb,
                             const float* __restrict__ w,
                             const float* __restrict__ bias) {
    __shared__ float s_zq[4096]; // [d][pos]
    __shared__ int   s_i[64];
    int b = blockIdx.x, tid = threadIdx.x;
    if (tid < 64) s_i[tid] = g_idx[b * 64 + tid];
    __syncthreads();
    for (int e = tid; e < 4096; e += 256) {
        int d = e >> 6, pos = e & 63;
        s_zq[e] = __ldg(cb + s_i[pos] * 64 + d);
    }
    __syncthreads();
    int pos = tid & 63, hg = tid >> 6;
    for (int h = 0; h < 32; h++) {
        int hc = hg * 32 + h;
        float acc = __ldg(bias + hc);
        const float* wr = w + hc * 64;
#pragma unroll 8
        for (int d = 0; d < 64; d++) acc += __ldg(wr + d) * s_zq[d * 64 + pos];
        g_yp[b * 8192 + hc * 64 + pos] = pack_hl(fmaxf(acc, 0.f));
    }
}

// ================= dconv1 weight-subset precompute: 25 matrices [m][ic][oc] =================
__global__ void w25_kernel(const float* __restrict__ w) {
    int g = blockIdx.x * 256 + threadIdx.x;
    if (g >= 25 * 16384) return;
    int m = g >> 14; int r = g & 16383; int ic = r & 127; int oc = r >> 7;
    int sy = m / 5, sx = m - sy * 5;
    const int mask[5] = {1, 4, 3, 6, 7};
    float s = 0.f;
    for (int j = 0; j < 3; j++) if ((mask[sy] >> j) & 1)
        for (int i = 0; i < 3; i++) if ((mask[sx] >> i) & 1)
            s += __ldg(w + ((oc * 128 + ic) * 3 + j) * 3 + i);
    g_w25[(m * 128 + ic) * 128 + oc] = s;
}

// ================= dconv1 weights -> bf16 h/l split, A layout [m][q][oc][k16pairs] =================
__global__ void w25bf_kernel() {
    int e = blockIdx.x * 256 + threadIdx.x;  // 25*4*128*16 = 204800
    if (e >= 204800) return;
    int kw = e & 15, oc = (e >> 4) & 127, q = (e >> 11) & 3, m = e >> 13;
    int ic = q * 32 + 2 * kw;
    float v0 = g_w25[(m * 128 + ic) * 128 + oc];
    float v1 = g_w25[(m * 128 + ic + 1) * 128 + oc];
    __nv_bfloat16 h0 = __float2bfloat16(v0), h1 = __float2bfloat16(v1);
    __nv_bfloat16 l0 = __float2bfloat16(v0 - __bfloat162float(h0));
    __nv_bfloat16 l1 = __float2bfloat16(v1 - __bfloat162float(h1));
    g_wd1h[e] = (uint32_t)__bfloat16_as_ushort(h0) | ((uint32_t)__bfloat16_as_ushort(h1) << 16);
    g_wd1l[e] = (uint32_t)__bfloat16_as_ushort(l0) | ((uint32_t)__bfloat16_as_ushort(l1) << 16);
}

// ================= dconv1 via mma.sync bf16 2-split 3-pass =================
// grid (32 b, 9 job), 256 thr (8 warps). C[oc128, pos64]; warp tile 32 oc x 32 pos.
// Per vt: sum over m-passes of W25m[oc][ic] * Ym[ic][pos] (shifted, masked).
__device__ const int c_vt9[9] = {0, 2, 6, 8, 1, 3, 5, 7, 4};  // heavy (corner) first
__global__ void __launch_bounds__(256) dconv1_mma_kernel(const float* __restrict__ bias) {
    __shared__ float s_bias[128];
    __shared__ __align__(16) char pAH[10240];  // [oc128][80B] = 32 k bf16 + 16B pad
    __shared__ __align__(16) char pAL[10240];
    __shared__ __align__(16) char pBH[4608];   // [k32][144B] = 64 pos bf16 + 16B pad
    __shared__ __align__(16) char pBL[4608];
    uint32_t uAH = smem_u32(pAH), uAL = smem_u32(pAL);
    uint32_t uBH = smem_u32(pBH), uBL = smem_u32(pBL);

    int b = blockIdx.x;
    int vt = c_vt9[blockIdx.y];
    int tid = threadIdx.x, wid = tid >> 5, lane = tid & 31;
    int wm = (wid & 3) * 32;        // oc offset
    int wn = (wid >> 2) * 32;       // pos offset

    if (tid < 128) s_bias[tid] = __ldg(bias + tid);

    int ty = vt / 3, tx = vt - ty * 3;
    int nyp, ys[2], ydy[2];
    if (ty == 0)      { nyp = 2; ys[0] = 0; ydy[0] = -1; ys[1] = 3; ydy[1] = 0; }
    else if (ty == 1) { nyp = 1; ys[0] = 4; ydy[0] = 0;  ys[1] = 0; ydy[1] = 0; }
    else              { nyp = 2; ys[0] = 2; ydy[0] = 0;  ys[1] = 1; ydy[1] = 1; }
    int nxp, xs[2], xdx[2];
    if (tx == 0)      { nxp = 2; xs[0] = 0; xdx[0] = -1; xs[1] = 3; xdx[1] = 0; }
    else if (tx == 1) { nxp = 1; xs[0] = 4; xdx[0] = 0;  xs[1] = 0; xdx[1] = 0; }
    else              { nxp = 2; xs[0] = 2; xdx[0] = 0;  xs[1] = 1; xdx[1] = 1; }

    float acc[2][4][4];
#pragma unroll
    for (int mt = 0; mt < 2; mt++)
#pragma unroll
        for (int nt = 0; nt < 4; nt++)
#pragma unroll
            for (int i = 0; i < 4; i++) acc[mt][nt][i] = 0.f;

    // B staging coords: posS fixed, kgrp covers 8 k each
    int posS = tid & 63, kgrp = tid >> 6;
    int gyp = posS >> 3, gxp = posS & 7;

    for (int a = 0; a < nyp; a++) {
        for (int c = 0; c < nxp; c++) {
            int m = ys[a] * 5 + xs[c];
            int dy = ydy[a], dx = xdx[c];
            int ny = gyp + dy, nx = gxp + dx;
            bool ok = ((unsigned)ny < 8u) && ((unsigned)nx < 8u);
            int np = ny * 8 + nx;
            for (int q = 0; q < 4; q++) {
                __syncthreads();
                // ---- stage A (weights) ----
                {
                    const uint32_t* gh = g_wd1h + ((m * 4 + q) << 11);
                    const uint32_t* gl = g_wd1l + ((m * 4 + q) << 11);
#pragma unroll
                    for (int j = 0; j < 8; j++) {
                        int e = j * 256 + tid;
                        int oc = e >> 4, kw = e & 15;
                        int off = oc * 20 + kw;
                        ((uint32_t*)pAH)[off] = __ldg(gh + e);
                        ((uint32_t*)pAL)[off] = __ldg(gl + e);
                    }
                }
                // ---- stage B (inputs, gathered + masked) ----
                {
                    const uint32_t* src = g_yp + b * 8192 + (q * 32) * 64 + np;
#pragma unroll
                    for (int j = 0; j < 8; j++) {
                        int kk = kgrp * 8 + j;
                        uint32_t u = ok ? __ldg(src + kk * 64) : 0u;
                        ((unsigned short*)(pBH + kk * 144))[posS] = (unsigned short)u;
                        ((unsigned short*)(pBL + kk * 144))[posS] = (unsigned short)(u >> 16);
                    }
                }
                __syncthreads();
                // ---- mma: 2 k16 steps x 2 mt x 4 nt x 3 passes ----
#pragma unroll
                for (int ks = 0; ks < 2; ks++) {
                    int kb = ks << 5;
                    uint32_t ah[2][4], al2[2][4];
#pragma unroll
                    for (int mt = 0; mt < 2; mt++) {
                        uint32_t off = (uint32_t)((wm + mt * 16 + (lane & 15)) * 80
                                                  + kb + ((lane >> 4) << 4));
                        ldm_x4(ah[mt], uAH + off);
                        ldm_x4(al2[mt], uAL + off);
                    }
#pragma unroll
                    for (int cg = 0; cg < 2; cg++) {
                        int n0 = wn + cg * 16;
                        uint32_t boff = (uint32_t)(((ks << 4) + (lane & 15)) * 144
                                                   + ((n0 + ((lane >> 4) << 3)) << 1));
                        uint32_t bh[4], bl[4];
                        ldm_x4_t(bh, uBH + boff);
                        ldm_x4_t(bl, uBL + boff);
#pragma unroll
                        for (int h2 = 0; h2 < 2; h2++) {
                            uint32_t b0h = bh[2 * h2], b1h = bh[2 * h2 + 1];
                            uint32_t b0l = bl[2 * h2], b1l = bl[2 * h2 + 1];
#pragma unroll
                            for (int mt = 0; mt < 2; mt++) {
                                float* ac = acc[mt][2 * cg + h2];
                                mma16816(ac, ah[mt],  b0h, b1h);
                                mma16816(ac, ah[mt],  b0l, b1l);
                                mma16816(ac, al2[mt], b0h, b1h);
                            }
                        }
                    }
                }
            }
        }
    }

    // ---- epilogue: bias + relu -> g_r9[b][vt][oc][pos] ----
    float* op = g_r9 + ((size_t)(b * 9 + vt) * 128) * 64;
    int quad = lane >> 2, tix = lane & 3;
#pragma unroll
    for (int mt = 0; mt < 2; mt++) {
        int row0 = wm + mt * 16 + quad;
        float b0v = s_bias[row0], b1v = s_bias[row0 + 8];
#pragma unroll
        for (int nt = 0; nt < 4; nt++) {
            int col0 = wn + nt * 8 + tix * 2;
            op[row0 * 64 + col0]       = fmaxf(acc[mt][nt][0] + b0v, 0.f);
            op[row0 * 64 + col0 + 1]   = fmaxf(acc[mt][nt][1] + b0v, 0.f);
            op[(row0 + 8) * 64 + col0]     = fmaxf(acc[mt][nt][2] + b1v, 0.f);
            op[(row0 + 8) * 64 + col0 + 1] = fmaxf(acc[mt][nt][3] + b1v, 0.f);
        }
    }
}

// ================= dconv2 1x1 (128->3) on 9 block values + scatter to full image =================
__global__ void dconv2_scatter_kernel(const float* __restrict__ w,
                                      const float* __restrict__ bias,
                                      float* __restrict__ xhat) {
    __shared__ float s_r[1152]; // [vt][oc]
    __shared__ float s_v[27];   // [vt][co]
    int pos = blockIdx.x, b = blockIdx.y;
    int tid = threadIdx.x;
    for (int e = tid; e < 1152; e += 128) {
        int vt = e >> 7, oc = e & 127;
        s_r[e] = g_r9[((size_t)(b * 9 + vt) * 128 + oc) * 64 + pos];
    }
    __syncthreads();
    if (tid < 27) {
        int vt = tid / 3, co = tid - vt * 3;
        float acc = __ldg(bias + co);
        const float* wr = w + co * 128;
        const float* rr = s_r + vt * 128;
#pragma unroll 8
        for (int oc = 0; oc < 128; oc++) acc += __ldg(wr + oc) * rr[oc];
        s_v[tid] = acc;
    }
    __syncthreads();
    int gy = pos >> 3, gx = pos & 7;
    for (int pp = tid; pp < 256; pp += 128) {
        int ly = pp >> 4, lx = pp & 15;
        int ty2 = (ly == 0) ? 0 : ((ly == 15) ? 2 : 1);
        int tx2 = (lx == 0) ? 0 : ((lx == 15) ? 2 : 1);
        int vtp = ty2 * 3 + tx2;
        int py = gy * 16 + ly, px = gx * 16 + lx;
#pragma unroll
        for (int co = 0; co < 3; co++)
            xhat[((b * 3 + co) * 128 + py) * 128 + px] = s_v[vtp * 3 + co];
    }
}

// ================= launch =================
extern "C" void kernel_launch(void* const* d_in, const int* in_sizes, int n_in,
                              void* d_out, int out_size) {
    const float* x   = (const float*)d_in[0];
    const float* ew1 = (const float*)d_in[1];
    const float* eb1 = (const float*)d_in[2];
    const float* ew2 = (const float*)d_in[3];
    const float* eb2 = (const float*)d_in[4];
    const float* pw  = (const float*)d_in[5];
    const float* pb  = (const float*)d_in[6];
    const float* cb  = (const float*)d_in[7];
    const float* dpw = (const float*)d_in[8];
    const float* dpb = (const float*)d_in[9];
    const float* dw1 = (const float*)d_in[10];
    const float* db1 = (const float*)d_in[11];
    const float* dw2 = (const float*)d_in[12];
    const float* db2 = (const float*)d_in[13];

    float* out   = (float*)d_out;
    float* xhat  = out;               // 32*3*128*128 = 1572864
    float* idxo  = out + 1572864;     // 32*8*8       = 2048
    float* losso = out + 1574912;     // 1
    float* zeo   = out + 1574913;     // 32*64*8*8    = 131072

    // order keeps enc2_main at the profiled launch ordinal (#4)
    w2t_kernel<<<576, 256>>>(ew2);
    w25_kernel<<<1600, 256>>>(dw1);
    enc1_kernel<<<dim3(64, 32), 256>>>(x, ew1, eb1);
    enc2_main_kernel<<<dim3(32, 4, 8), 256>>>();
    enc2_reduce_kernel<<<dim3(32, 2, 8), 256>>>(eb2);
    proj_kernel<<<32, 256>>>(pw, pb, zeo);
    vq_part_kernel<<<dim3(32, 4), 512>>>(zeo, cb);
    vq_final_kernel<<<32, 64>>>(idxo);
    finalize_loss_kernel<<<1, 1>>>(losso);
    w25bf_kernel<<<800, 256>>>();
    dproj_kernel<<<32, 256>>>(cb, dpw, dpb);
    dconv1_mma_kernel<<<dim3(32, 9), 256>>>(db1);
    dconv2_scatter_kernel<<<dim3(64, 32), 128>>>(dw2, db2, xhat);
}

// round 16
// speedup vs baseline: 4.3181x; 1.1611x over previous
#include <cuda_runtime.h>
#include <cuda_bf16.h>
#include <cstdint>

// ---------------- problem constants ----------------
// x:(32,3,128,128)  enc1->(32,128,64,64)  enc2->(32,128,32,32) pool->(32,128,8,8)
// proj-> z_e (32,64,8,8)  VQ K=512,D=64  dproj->(32,128,8,8) up x16 -> dconv1 -> dconv2 -> (32,3,128,128)

// ---------------- device scratch (no allocations allowed) ----------------
__device__ float g_h1[32 * 128 * 64 * 64];        // enc1 output fp32 (64 MB)
__device__ float g_p2[32 * 2 * 2 * 8 * 64 * 128]; // enc2 split-K partials (67 MB)
__device__ float g_hp[32 * 128 * 8 * 8];          // pooled encoder features
__device__ uint32_t g_yp[32 * 128 * 8 * 8];       // dproj output relu'd, packed bf16 h|l
__device__ float g_r9[32 * 9 * 128 * 64];         // dconv1: 9 values per 16x16 block
__device__ float g_w2t[128 * 9 * 128];            // enc2 weights transposed [ic][tap][oc]
__device__ uint32_t g_wd1h[25 * 4 * 128 * 16];    // dconv1 weights bf16-h [m][q][oc][kpair]
__device__ uint32_t g_wd1l[25 * 4 * 128 * 16];    // dconv1 weights bf16-l
__device__ int   g_idx[2048];
__device__ float g_loss_part[32];
__device__ float g_vqv[32 * 4 * 64];
__device__ int   g_vqi[32 * 4 * 64];

// ================= helpers =================
__device__ __forceinline__ uint32_t smem_u32(const void* p) {
    uint32_t a;
    asm("{ .reg .u64 t; cvta.to.shared.u64 t, %1; cvt.u32.u64 %0, t; }" : "=r"(a) : "l"(p));
    return a;
}
__device__ __forceinline__ void cp4(uint32_t dst, const void* src, int sz) {
    asm volatile("cp.async.ca.shared.global [%0], [%1], 4, %2;"
                 :: "r"(dst), "l"(src), "r"(sz) : "memory");
}
__device__ __forceinline__ void cp16(uint32_t dst, const void* src) {
    asm volatile("cp.async.ca.shared.global [%0], [%1], 16;"
                 :: "r"(dst), "l"(src) : "memory");
}
__device__ __forceinline__ void ldm_x4(uint32_t* r, uint32_t a) {
    asm volatile("ldmatrix.sync.aligned.m8n8.x4.shared.b16 {%0,%1,%2,%3}, [%4];"
                 : "=r"(r[0]), "=r"(r[1]), "=r"(r[2]), "=r"(r[3]) : "r"(a));
}
__device__ __forceinline__ void ldm_x4_t(uint32_t* r, uint32_t a) {
    asm volatile("ldmatrix.sync.aligned.m8n8.x4.trans.shared.b16 {%0,%1,%2,%3}, [%4];"
                 : "=r"(r[0]), "=r"(r[1]), "=r"(r[2]), "=r"(r[3]) : "r"(a));
}
__device__ __forceinline__ void mma16816(float* d, const uint32_t* a, uint32_t b0, uint32_t b1) {
    asm volatile("mma.sync.aligned.m16n8k16.row.col.f32.bf16.bf16.f32 "
                 "{%0,%1,%2,%3}, {%4,%5,%6,%7}, {%8,%9}, {%0,%1,%2,%3};"
                 : "+f"(d[0]), "+f"(d[1]), "+f"(d[2]), "+f"(d[3])
                 : "r"(a[0]), "r"(a[1]), "r"(a[2]), "r"(a[3]), "r"(b0), "r"(b1));
}
__device__ __forceinline__ uint32_t pack_hl(float v) {
    __nv_bfloat16 h = __float2bfloat16(v);
    __nv_bfloat16 l = __float2bfloat16(v - __bfloat162float(h));
    return (uint32_t)__bfloat16_as_ushort(h) | ((uint32_t)__bfloat16_as_ushort(l) << 16);
}

// ================= enc2 weight transpose: w[oc][ic][ky][kx] -> g_w2t[ic][tap][oc] =================
__global__ void w2t_kernel(const float* __restrict__ w) {
    int e = blockIdx.x * 256 + threadIdx.x;   // 147456 elements
    if (e >= 147456) return;
    int oc = e & 127; int t = e >> 7;         // t = ic*9 + tap
    int tap = t % 9; int icf = t / 9;
    g_w2t[e] = __ldg(w + (oc * 128 + icf) * 9 + tap);
}

// ================= dconv1 weights: fused subset-sum + bf16 h/l split =================
// subset masks: 0:{0} 1:{2} 2:{0,1} 3:{1,2} 4:{0,1,2};  m = sy*5 + sx
__global__ void w25bf_kernel(const float* __restrict__ w) {
    int e = blockIdx.x * 256 + threadIdx.x;  // 25*4*128*16 = 204800
    if (e >= 204800) return;
    int kw = e & 15, oc = (e >> 4) & 127, q = (e >> 11) & 3, m = e >> 13;
    int sy = m / 5, sx = m - sy * 5;
    const int mask[5] = {1, 4, 3, 6, 7};
    int ic = q * 32 + 2 * kw;
    float v0 = 0.f, v1 = 0.f;
    for (int j = 0; j < 3; j++) if ((mask[sy] >> j) & 1)
        for (int i = 0; i < 3; i++) if ((mask[sx] >> i) & 1) {
            v0 += __ldg(w + ((oc * 128 + ic) * 3 + j) * 3 + i);
            v1 += __ldg(w + ((oc * 128 + ic + 1) * 3 + j) * 3 + i);
        }
    __nv_bfloat16 h0 = __float2bfloat16(v0), h1 = __float2bfloat16(v1);
    __nv_bfloat16 l0 = __float2bfloat16(v0 - __bfloat162float(h0));
    __nv_bfloat16 l1 = __float2bfloat16(v1 - __bfloat162float(h1));
    g_wd1h[e] = (uint32_t)__bfloat16_as_ushort(h0) | ((uint32_t)__bfloat16_as_ushort(h1) << 16);
    g_wd1l[e] = (uint32_t)__bfloat16_as_ushort(l0) | ((uint32_t)__bfloat16_as_ushort(l1) << 16);
}

// ================= encoder conv1: 3->128, 3x3, stride 2, pad 1, relu =================
__global__ void enc1_kernel(const float* __restrict__ x,
                            const float* __restrict__ w,
                            const float* __restrict__ bias) {
    __shared__ float ws[3456]; // [c][ky][kx][128]
    int oy = blockIdx.x, b = blockIdx.y;
    int tid = threadIdx.x;
    for (int e = tid; e < 3456; e += 256) {
        int oc = e & 127; int t = e >> 7;
        int c = t / 9; int r = t - c * 9; int ky = r / 3, kx = r - ky * 3;
        ws[e] = w[((oc * 3 + c) * 3 + ky) * 3 + kx];
    }
    __syncthreads();
    int ox = tid & 63, ocg = tid >> 6;
    float acc[32];
#pragma unroll
    for (int i = 0; i < 32; i++) acc[i] = __ldg(bias + ocg * 32 + i);
    const float* xb = x + b * 3 * 128 * 128;
#pragma unroll
    for (int c = 0; c < 3; c++) {
#pragma unroll
        for (int ky = 0; ky < 3; ky++) {
            int iy = 2 * oy + ky - 1;
#pragma unroll
            for (int kx = 0; kx < 3; kx++) {
                int ix = 2 * ox + kx - 1;
                float xv = 0.f;
                if ((unsigned)iy < 128u && (unsigned)ix < 128u)
                    xv = __ldg(xb + (c * 128 + iy) * 128 + ix);
                const float* wp = &ws[((c * 3 + ky) * 3 + kx) * 128 + ocg * 32];
#pragma unroll
                for (int q = 0; q < 8; q++) {
                    float4 wv = *(const float4*)(wp + q * 4);
                    acc[q * 4 + 0] += wv.x * xv;
                    acc[q * 4 + 1] += wv.y * xv;
                    acc[q * 4 + 2] += wv.z * xv;
                    acc[q * 4 + 3] += wv.w * xv;
                }
            }
        }
    }
    float* op = g_h1 + ((b * 128 + ocg * 32) * 64 + oy) * 64 + ox;
#pragma unroll
    for (int i = 0; i < 32; i++) op[i * 64 * 64] = fmaxf(acc[i], 0.f);
}

// ================= encoder conv2 main: cp.async double-buffered split-K (fp32) =================
// grid (32 b, 4 y=[ocg|half], 8 gy), 256 thr; tile 64 oc x (4 rows x 32 cols) over 64 ic,
// processed as 16 chunks of 4 ic with cp.async prefetch into alternating buffers.
__global__ void __launch_bounds__(256, 4) enc2_main_kernel() {
    __shared__ __align__(16) float smbuf[2][4752];  // per buf: s_in 4*612 | s_w 4*576

    int b = blockIdx.x;
    int ocg = blockIdx.y >> 1, half = blockIdx.y & 1;
    int gy = blockIdx.z;
    int tid = threadIdx.x, lane = tid & 31, wid = tid >> 5;
    int ocq = wid;
    int r = lane >> 3, cg = lane & 7;

    // staging roles: warp-pair per ic, even/odd de-strided layout
    int ic_l = wid >> 1;
    int sub = wid & 1;
    int off0 = (lane & 1) ? ((lane - 1) >> 1) : (32 + (lane >> 1));
    int off1 = (lane & 1) ? ((lane + 31) >> 1) : (32 + ((lane + 32) >> 1));
    int iy0 = gy * 8 - 1;

    uint32_t sb0 = smem_u32(&smbuf[0][0]);
    uint32_t sb1 = smem_u32(&smbuf[1][0]);

    float acc[8][4];
#pragma unroll
    for (int i = 0; i < 8; i++)
#pragma unroll
        for (int p = 0; p < 4; p++) acc[i][p] = 0.f;

    auto stage = [&](int c, int bufi) {
        uint32_t sbase = bufi ? sb1 : sb0;
        // ---- inputs (cp.async 4B, zero-fill via src-size 0) ----
        int ic = half * 64 + c * 4 + ic_l;
        const float* src = g_h1 + (((size_t)b * 128 + ic) * 64) * 64;
        uint32_t dIn = sbase + (uint32_t)(ic_l * 612) * 4u;
        int nr = sub ? 4 : 5;
#pragma unroll
        for (int j = 0; j < 5; j++) {
            if (j < nr) {
                int rr = 2 * j + sub;
                int iy = iy0 + rr;
                bool rowok = (unsigned)iy < 64u;
                const float* srow = src + iy * 64;
                int ix0 = lane - 1;
                bool ok0 = rowok && ((unsigned)ix0 < 64u);
                cp4(dIn + (uint32_t)(rr * 68 + off0) * 4u, ok0 ? (srow + ix0) : src, ok0 ? 4 : 0);
                int ix1 = lane + 31;
                bool ok1 = rowok && (ix1 < 64);
                cp4(dIn + (uint32_t)(rr * 68 + off1) * 4u, ok1 ? (srow + ix1) : src, ok1 ? 4 : 0);
            }
        }
        if (sub == 1 && lane < 9) {
            int iy = iy0 + lane;
            bool ok = (unsigned)iy < 64u;
            cp4(dIn + (uint32_t)(lane * 68 + 64) * 4u, ok ? (src + iy * 64 + 63) : src, ok ? 4 : 0);
        }
        // ---- weights (cp.async 16B, contiguous) ----
        uint32_t dW = sbase + 2448u * 4u;
#pragma unroll
        for (int t3 = 0; t3 < 3; t3++) {
            int t = t3 * 256 + tid;
            if (t < 576) {
                int icl = t / 144;
                int rem = t - icl * 144;
                int tap = rem >> 4;
                int o4 = rem & 15;
                int ic2 = half * 64 + c * 4 + icl;
                const float* s = g_w2t + ((size_t)ic2 * 9 + tap) * 128 + ocg * 64 + o4 * 4;
                cp16(dW + (uint32_t)((icl * 9 + tap) * 64 + o4 * 4) * 4u, s);
            }
        }
    };

    stage(0, 0);
    asm volatile("cp.async.commit_group;" ::: "memory");

    for (int c = 0; c < 16; c++) {
        if (c < 15) {
            stage(c + 1, (c + 1) & 1);
            asm volatile("cp.async.commit_group;" ::: "memory");
            asm volatile("cp.async.wait_group 1;" ::: "memory");
        } else {
            asm volatile("cp.async.wait_group 0;" ::: "memory");
        }
        __syncthreads();
        const float* s_in = smbuf[c & 1];
        const float* s_w  = smbuf[c & 1] + 2448;
#pragma unroll
        for (int ic = 0; ic < 4; ic++) {
            const float* sib = s_in + ic * 612;
            const float* swb = s_w + ic * 576 + ocq * 8;
#pragma unroll
            for (int ky = 0; ky < 3; ky++) {
                const float* rp = sib + (2 * r + ky) * 68;
                float4 E4 = *(const float4*)(rp + 4 * cg);
                float4 O4 = *(const float4*)(rp + 32 + 4 * cg);
                float  O1 = rp[36 + 4 * cg];
                float in0[4] = {O4.x, O4.y, O4.z, O4.w};   // kx=0
                float in1[4] = {E4.x, E4.y, E4.z, E4.w};   // kx=1
                float in2[4] = {O4.y, O4.z, O4.w, O1};     // kx=2
#pragma unroll
                for (int kx = 0; kx < 3; kx++) {
                    const float* wp = swb + (ky * 3 + kx) * 64;
                    float4 wA = *(const float4*)wp;
                    float4 wB = *(const float4*)(wp + 4);
                    float wr[8] = {wA.x, wA.y, wA.z, wA.w, wB.x, wB.y, wB.z, wB.w};
                    const float* in = (kx == 0) ? in0 : (kx == 1) ? in1 : in2;
#pragma unroll
                    for (int i = 0; i < 8; i++) {
#pragma unroll
                        for (int p = 0; p < 4; p++) acc[i][p] += wr[i] * in[p];
                    }
                }
            }
        }
        __syncthreads();
    }

    float* op = g_p2 + ((((size_t)b * 2 + ocg) * 2 + half) * 8 + gy) * 8192;
#pragma unroll
    for (int i = 0; i < 8; i++) {
        float4 v = make_float4(acc[i][0], acc[i][1], acc[i][2], acc[i][3]);
        *(float4*)(op + (ocq * 8 + i) * 128 + r * 32 + 4 * cg) = v;
    }
}

// ================= enc2 reduce: sum halves + bias + relu + 4x4 pool =================
__global__ void enc2_reduce_kernel(const float* __restrict__ bias) {
    int b = blockIdx.x, ocg = blockIdx.y, gy = blockIdx.z;
    int tid = threadIdx.x;
    const float* p0 = g_p2 + ((((size_t)b * 2 + ocg) * 2 + 0) * 8 + gy) * 8192;
    const float* p1 = g_p2 + ((((size_t)b * 2 + ocg) * 2 + 1) * 8 + gy) * 8192;
#pragma unroll
    for (int t = 0; t < 2; t++) {
        int o = t * 256 + tid;       // 0..511
        int oc = o >> 3, gx = o & 7;
        float bv = __ldg(bias + ocg * 64 + oc);
        float s = 0.f;
#pragma unroll
        for (int r = 0; r < 4; r++) {
            float4 a = *(const float4*)(p0 + oc * 128 + r * 32 + 4 * gx);
            float4 c = *(const float4*)(p1 + oc * 128 + r * 32 + 4 * gx);
            s += fmaxf(a.x + c.x + bv, 0.f) + fmaxf(a.y + c.y + bv, 0.f)
               + fmaxf(a.z + c.z + bv, 0.f) + fmaxf(a.w + c.w + bv, 0.f);
        }
        g_hp[((b * 128 + ocg * 64 + oc) * 8 + gy) * 8 + gx] = s * (1.f / 16.f);
    }
}

// ================= proj 1x1: 128 -> 64 (fp32 exact, feeds argmin), grid (32,2) =================
__global__ void proj_kernel(const float* __restrict__ w,
                            const float* __restrict__ bias,
                            float* __restrict__ zout) {
    __shared__ float s_hp[8192]; // [hc][pos]
    int b = blockIdx.x, half = blockIdx.y, tid = threadIdx.x;
    for (int e = tid; e < 8192; e += 256) s_hp[e] = g_hp[b * 8192 + e];
    __syncthreads();
    int pos = tid & 63, dg = tid >> 6;
    for (int dl = 0; dl < 8; dl++) {
        int d = half * 32 + dg * 8 + dl;
        float acc = __ldg(bias + d);
        const float* wr = w + d * 128;
#pragma unroll 8
        for (int hc = 0; hc < 128; hc++) acc += __ldg(wr + hc) * s_hp[hc * 64 + pos];
        zout[(b * 64 + d) * 64 + pos] = acc;
    }
}

// ================= vector quantizer: 4-wide partials + final reduce =================
__global__ void __launch_bounds__(512) vq_part_kernel(const float* __restrict__ z,
                                                      const float* __restrict__ cb) {
    __shared__ float s_z[64 * 68];
    __shared__ float s_c[64 * 68];
    __shared__ float s_rv[512];
    __shared__ int   s_ri[512];
    int b = blockIdx.x, part = blockIdx.y, tid = threadIdx.x;
    int pos = tid & 63, kq = tid >> 6;
    for (int e = tid; e < 4096; e += 512) {
        int d = e >> 6, p = e & 63;
        s_z[p * 68 + d] = z[(b * 64 + d) * 64 + p];
    }
    float bestv = 3.4e38f; int besti = 0;
    for (int t = 0; t < 2; t++) {
        __syncthreads();
        for (int e = tid; e < 4096; e += 512) {
            int k = e >> 6, d = e & 63;
            s_c[k * 68 + d] = __ldg(cb + ((part * 2 + t) * 64 + k) * 64 + d);
        }
        __syncthreads();
        float accq[8];
#pragma unroll
        for (int j = 0; j < 8; j++) accq[j] = 0.f;
        const float* zp = s_z + pos * 68;
        for (int d = 0; d < 64; d += 4) {
            float4 z4 = *(const float4*)(zp + d);
#pragma unroll
            for (int j = 0; j < 8; j++) {
                float4 c4 = *(const float4*)(s_c + (kq * 8 + j) * 68 + d);
                float d0 = c4.x - z4.x; accq[j] += d0 * d0;
                float d1 = c4.y - z4.y; accq[j] += d1 * d1;
                float d2 = c4.z - z4.z; accq[j] += d2 * d2;
                float d3 = c4.w - z4.w; accq[j] += d3 * d3;
            }
        }
#pragma unroll
        for (int j = 0; j < 8; j++) {
            int k = (part * 2 + t) * 64 + kq * 8 + j;
            if (accq[j] < bestv) { bestv = accq[j]; besti = k; }
        }
    }
    s_rv[tid] = bestv; s_ri[tid] = besti;
    __syncthreads();
    if (tid < 64) {
        float bv = s_rv[tid]; int bi = s_ri[tid];
#pragma unroll
        for (int q = 1; q < 8; q++) {
            float v = s_rv[q * 64 + tid]; int i2 = s_ri[q * 64 + tid];
            if (v < bv || (v == bv && i2 < bi)) { bv = v; bi = i2; }
        }
        g_vqv[(b * 4 + part) * 64 + tid] = bv;
        g_vqi[(b * 4 + part) * 64 + tid] = bi;
    }
}

__global__ void vq_final_kernel(float* __restrict__ idx_out) {
    __shared__ float sv[64];
    int b = blockIdx.x, tid = threadIdx.x;  // tid = pos
    float bv = g_vqv[(b * 4 + 0) * 64 + tid];
    int   bi = g_vqi[(b * 4 + 0) * 64 + tid];
#pragma unroll
    for (int part = 1; part < 4; part++) {
        float v = g_vqv[(b * 4 + part) * 64 + tid];
        int  i2 = g_vqi[(b * 4 + part) * 64 + tid];
        if (v < bv || (v == bv && i2 < bi)) { bv = v; bi = i2; }
    }
    int n = b * 64 + tid;
    g_idx[n] = bi;
    idx_out[n] = (float)bi;
    sv[tid] = bv;
    __syncthreads();
    if (tid == 0) {
        float s = 0.f;
        for (int i = 0; i < 64; i++) s += sv[i];
        g_loss_part[b] = s;
    }
}

__global__ void finalize_loss_kernel(float* __restrict__ out) {
    float s = 0.f;
    for (int i = 0; i < 32; i++) s += g_loss_part[i];
    out[0] = s * (1.25f / 131072.f);
}

// ================= dproj 1x1: 64 -> 128, relu -> packed bf16 h|l, grid (32,2) =================
__global__ void dproj_kernel(const float* __restrict__ cb,
                             const float* __restrict__ w,
                             const float* __restrict__ bias) {
    __shared__ float s_zq[4096]; // [d][pos]
    __shared__ int   s_i[64];
    int b = blockIdx.x, half = blockIdx.y, tid = threadIdx.x;
    if (tid < 64) s_i[tid] = g_idx[b * 64 + tid];
    __syncthreads();
    for (int e = tid; e < 4096; e += 256) {
        int d = e >> 6, pos = e & 63;
        s_zq[e] = __ldg(cb + s_i[pos] * 64 + d);
    }
    __syncthreads();
    int pos = tid & 63, hg = tid >> 6;
    for (int h = 0; h < 16; h++) {
        int hc = half * 64 + hg * 16 + h;
        float acc = __ldg(bias + hc);
        const float* wr = w + hc * 64;
#pragma unroll 8
        for (int d = 0; d < 64; d++) acc += __ldg(wr + d) * s_zq[d * 64 + pos];
        g_yp[b * 8192 + hc * 64 + pos] = pack_hl(fmaxf(acc, 0.f));
    }
}

// ================= dconv1 via mma.sync bf16 2-split 3-pass =================
// grid (32 b, 9 job), 256 thr (8 warps). C[oc128, pos64]; warp tile 32 oc x 32 pos.
__device__ const int c_vt9[9] = {0, 2, 6, 8, 1, 3, 5, 7, 4};  // heavy (corner) first
__global__ void __launch_bounds__(256) dconv1_mma_kernel(const float* __restrict__ bias) {
    __shared__ float s_bias[128];
    __shared__ __align__(16) char pAH[10240];  // [oc128][80B] = 32 k bf16 + 16B pad
    __shared__ __align__(16) char pAL[10240];
    __shared__ __align__(16) char pBH[4608];   // [k32][144B] = 64 pos bf16 + 16B pad
    __shared__ __align__(16) char pBL[4608];
    uint32_t uAH = smem_u32(pAH), uAL = smem_u32(pAL);
    uint32_t uBH = smem_u32(pBH), uBL = smem_u32(pBL);

    int b = blockIdx.x;
    int vt = c_vt9[blockIdx.y];
    int tid = threadIdx.x, wid = tid >> 5, lane = tid & 31;
    int wm = (wid & 3) * 32;        // oc offset
    int wn = (wid >> 2) * 32;       // pos offset

    if (tid < 128) s_bias[tid] = __ldg(bias + tid);

    int ty = vt / 3, tx = vt - ty * 3;
    int nyp, ys[2], ydy[2];
    if (ty == 0)      { nyp = 2; ys[0] = 0; ydy[0] = -1; ys[1] = 3; ydy[1] = 0; }
    else if (ty == 1) { nyp = 1; ys[0] = 4; ydy[0] = 0;  ys[1] = 0; ydy[1] = 0; }
    else              { nyp = 2; ys[0] = 2; ydy[0] = 0;  ys[1] = 1; ydy[1] = 1; }
    int nxp, xs[2], xdx[2];
    if (tx == 0)      { nxp = 2; xs[0] = 0; xdx[0] = -1; xs[1] = 3; xdx[1] = 0; }
    else if (tx == 1) { nxp = 1; xs[0] = 4; xdx[0] = 0;  xs[1] = 0; xdx[1] = 0; }
    else              { nxp = 2; xs[0] = 2; xdx[0] = 0;  xs[1] = 1; xdx[1] = 1; }

    float acc[2][4][4];
#pragma unroll
    for (int mt = 0; mt < 2; mt++)
#pragma unroll
        for (int nt = 0; nt < 4; nt++)
#pragma unroll
            for (int i = 0; i < 4; i++) acc[mt][nt][i] = 0.f;

    int posS = tid & 63, kgrp = tid >> 6;
    int gyp = posS >> 3, gxp = posS & 7;

    for (int a = 0; a < nyp; a++) {
        for (int c = 0; c < nxp; c++) {
            int m = ys[a] * 5 + xs[c];
            int dy = ydy[a], dx = xdx[c];
            int ny = gyp + dy, nx = gxp + dx;
            bool ok = ((unsigned)ny < 8u) && ((unsigned)nx < 8u);
            int np = ny * 8 + nx;
            for (int q = 0; q < 4; q++) {
                __syncthreads();
                {
                    const uint32_t* gh = g_wd1h + ((m * 4 + q) << 11);
                    const uint32_t* gl = g_wd1l + ((m * 4 + q) << 11);
#pragma unroll
                    for (int j = 0; j < 8; j++) {
                        int e = j * 256 + tid;
                        int oc = e >> 4, kw = e & 15;
                        int off = oc * 20 + kw;
                        ((uint32_t*)pAH)[off] = __ldg(gh + e);
                        ((uint32_t*)pAL)[off] = __ldg(gl + e);
                    }
                }
                {
                    const uint32_t* src = g_yp + b * 8192 + (q * 32) * 64 + np;
#pragma unroll
                    for (int j = 0; j < 8; j++) {
                        int kk = kgrp * 8 + j;
                        uint32_t u = ok ? __ldg(src + kk * 64) : 0u;
                        ((unsigned short*)(pBH + kk * 144))[posS] = (unsigned short)u;
                        ((unsigned short*)(pBL + kk * 144))[posS] = (unsigned short)(u >> 16);
                    }
                }
                __syncthreads();
#pragma unroll
                for (int ks = 0; ks < 2; ks++) {
                    int kb = ks << 5;
                    uint32_t ah[2][4], al2[2][4];
#pragma unroll
                    for (int mt = 0; mt < 2; mt++) {
                        uint32_t off = (uint32_t)((wm + mt * 16 + (lane & 15)) * 80
                                                  + kb + ((lane >> 4) << 4));
                        ldm_x4(ah[mt], uAH + off);
                        ldm_x4(al2[mt], uAL + off);
                    }
#pragma unroll
                    for (int cg = 0; cg < 2; cg++) {
                        int n0 = wn + cg * 16;
                        uint32_t boff = (uint32_t)(((ks << 4) + (lane & 15)) * 144
                                                   + ((n0 + ((lane >> 4) << 3)) << 1));
                        uint32_t bh[4], bl[4];
                        ldm_x4_t(bh, uBH + boff);
                        ldm_x4_t(bl, uBL + boff);
#pragma unroll
                        for (int h2 = 0; h2 < 2; h2++) {
                            uint32_t b0h = bh[2 * h2], b1h = bh[2 * h2 + 1];
                            uint32_t b0l = bl[2 * h2], b1l = bl[2 * h2 + 1];
#pragma unroll
                            for (int mt = 0; mt < 2; mt++) {
                                float* ac = acc[mt][2 * cg + h2];
                                mma16816(ac, ah[mt],  b0h, b1h);
                                mma16816(ac, ah[mt],  b0l, b1l);
                                mma16816(ac, al2[mt], b0h, b1h);
                            }
                        }
                    }
                }
            }
        }
    }

    float* op = g_r9 + ((size_t)(b * 9 + vt) * 128) * 64;
    int quad = lane >> 2, tix = lane & 3;
#pragma unroll
    for (int mt = 0; mt < 2; mt++) {
        int row0 = wm + mt * 16 + quad;
        float b0v = s_bias[row0], b1v = s_bias[row0 + 8];
#pragma unroll
        for (int nt = 0; nt < 4; nt++) {
            int col0 = wn + nt * 8 + tix * 2;
            op[row0 * 64 + col0]       = fmaxf(acc[mt][nt][0] + b0v, 0.f);
            op[row0 * 64 + col0 + 1]   = fmaxf(acc[mt][nt][1] + b0v, 0.f);
            op[(row0 + 8) * 64 + col0]     = fmaxf(acc[mt][nt][2] + b1v, 0.f);
            op[(row0 + 8) * 64 + col0 + 1] = fmaxf(acc[mt][nt][3] + b1v, 0.f);
        }
    }
}

// ================= dconv2 1x1 (128->3) + scatter, coalesced 8-pos blocks =================
// grid (8 posg, 32 b), 128 thr.
__global__ void dconv2_scatter_kernel(const float* __restrict__ w,
                                      const float* __restrict__ bias,
                                      float* __restrict__ xhat) {
    __shared__ float s_r[9 * 128 * 9];   // [vt][oc][pos8 pad9]
    __shared__ float s_w[384];           // [co][oc]
    __shared__ float s_v[216];           // [vt][co][pos8]
    int pg = blockIdx.x, b = blockIdx.y;
    int tid = threadIdx.x;
    for (int e = tid; e < 384; e += 128) s_w[e] = __ldg(w + e);
    for (int e = tid; e < 9216; e += 128) {
        int pp = e & 7, oc = (e >> 3) & 127, vt = e >> 10;
        s_r[(vt * 128 + oc) * 9 + pp] =
            g_r9[((size_t)(b * 9 + vt) * 128 + oc) * 64 + pg * 8 + pp];
    }
    __syncthreads();
    for (int t = tid; t < 216; t += 128) {
        int vt = t / 24, rem = t - vt * 24;
        int co = rem >> 3, pp = rem & 7;
        float acc = __ldg(bias + co);
        const float* rr = s_r + (vt * 128) * 9 + pp;
        const float* wr = s_w + co * 128;
#pragma unroll 8
        for (int oc = 0; oc < 128; oc++) acc += wr[oc] * rr[oc * 9];
        s_v[(vt * 3 + co) * 8 + pp] = acc;
    }
    __syncthreads();
#pragma unroll
    for (int pp = 0; pp < 8; pp++) {
        int pos = pg * 8 + pp;
        int gy = pos >> 3, gx = pos & 7;
        for (int t = tid; t < 256; t += 128) {
            int ly = t >> 4, lx = t & 15;
            int ty2 = (ly == 0) ? 0 : ((ly == 15) ? 2 : 1);
            int tx2 = (lx == 0) ? 0 : ((lx == 15) ? 2 : 1);
            int vtp = ty2 * 3 + tx2;
            int py = gy * 16 + ly, px = gx * 16 + lx;
#pragma unroll
            for (int co = 0; co < 3; co++)
                xhat[((b * 3 + co) * 128 + py) * 128 + px] = s_v[(vtp * 3 + co) * 8 + pp];
        }
    }
}

// ================= launch =================
extern "C" void kernel_launch(void* const* d_in, const int* in_sizes, int n_in,
                              void* d_out, int out_size) {
    const float* x   = (const float*)d_in[0];
    const float* ew1 = (const float*)d_in[1];
    const float* eb1 = (const float*)d_in[2];
    const float* ew2 = (const float*)d_in[3];
    const float* eb2 = (const float*)d_in[4];
    const float* pw  = (const float*)d_in[5];
    const float* pb  = (const float*)d_in[6];
    const float* cb  = (const float*)d_in[7];
    const float* dpw = (const float*)d_in[8];
    const float* dpb = (const float*)d_in[9];
    const float* dw1 = (const float*)d_in[10];
    const float* db1 = (const float*)d_in[11];
    const float* dw2 = (const float*)d_in[12];
    const float* db2 = (const float*)d_in[13];

    float* out   = (float*)d_out;
    float* xhat  = out;               // 32*3*128*128 = 1572864
    float* idxo  = out + 1572864;     // 32*8*8       = 2048
    float* losso = out + 1574912;     // 1
    float* zeo   = out + 1574913;     // 32*64*8*8    = 131072

    // order keeps enc2_main at the profiled launch ordinal (#4)
    w2t_kernel<<<576, 256>>>(ew2);
    w25bf_kernel<<<800, 256>>>(dw1);
    enc1_kernel<<<dim3(64, 32), 256>>>(x, ew1, eb1);
    enc2_main_kernel<<<dim3(32, 4, 8), 256>>>();
    enc2_reduce_kernel<<<dim3(32, 2, 8), 256>>>(eb2);
    proj_kernel<<<dim3(32, 2), 256>>>(pw, pb, zeo);
    vq_part_kernel<<<dim3(32, 4), 512>>>(zeo, cb);
    vq_final_kernel<<<32, 64>>>(idxo);
    finalize_loss_kernel<<<1, 1>>>(losso);
    dproj_kernel<<<dim3(32, 2), 256>>>(cb, dpw, dpb);
    dconv1_mma_kernel<<<dim3(32, 9), 256>>>(db1);
    dconv2_scatter_kernel<<<dim3(8, 32), 128>>>(dw2, db2, xhat);
}